// round 2
// baseline (speedup 1.0000x reference)
#include <cuda_runtime.h>
#include <cstdint>

#define N_NODES 100000
#define IN_F    512
#define HID     128
#define NCLS    32

// ---------------- scratch (static device globals; no allocations) ----------
__device__ __align__(16) float g_dinv[N_NODES];                    // deg -> dinv in place
__device__ __align__(16) float g_h  [(size_t)N_NODES * HID];       // x @ W1
__device__ __align__(16) float g_a1 [(size_t)N_NODES * HID];       // aggregated layer-1 (pre-bias/relu)
__device__ __align__(16) float g_h2 [(size_t)N_NODES * NCLS];      // relu(a1+b1) @ W2

// Vectorized global reduction (sm_90+): 1 LTS op per 16B instead of 4.
__device__ __forceinline__ void red_add_v4(float* addr, float4 v) {
    asm volatile("red.global.add.v4.f32 [%0], {%1, %2, %3, %4};"
                 :: "l"(addr), "f"(v.x), "f"(v.y), "f"(v.z), "f"(v.w)
                 : "memory");
}

// ---------------- degree / dinv -------------------------------------------
__global__ void k_deg_init() {
    int i = blockIdx.x * blockDim.x + threadIdx.x;
    if (i < N_NODES) g_dinv[i] = 1.0f;   // self loop
}

__global__ void k_deg_count(const int* __restrict__ dst, int E) {
    int e = blockIdx.x * blockDim.x + threadIdx.x;
    if (e < E) atomicAdd(&g_dinv[dst[e]], 1.0f);
}

__global__ void k_dinv() {
    int i = blockIdx.x * blockDim.x + threadIdx.x;
    if (i < N_NODES) g_dinv[i] = rsqrtf(g_dinv[i]);  // deg >= 1 always
}

// ---------------- GEMM1: h = x @ W1  (M=100000, K=512, N=128) -------------
__global__ __launch_bounds__(256) void k_gemm1(const float* __restrict__ A,
                                               const float* __restrict__ W) {
    constexpr int BM = 128, BK = 8;
    __shared__ float As[BK][BM];   // transposed A tile
    __shared__ float Bs[BK][HID];

    const int tid  = threadIdx.x;
    const int tx   = tid & 15;     // n-dim (8 cols each)
    const int ty   = tid >> 4;     // m-dim (8 rows each)
    const int row0 = blockIdx.x * BM;

    const int a_row = tid >> 1;          // 0..127
    const int a_k4  = (tid & 1) * 4;     // 0 or 4
    const int b_k   = tid >> 5;          // 0..7
    const int b_n4  = (tid & 31) * 4;    // 0..124

    float acc[8][8];
    #pragma unroll
    for (int i = 0; i < 8; i++)
        #pragma unroll
        for (int j = 0; j < 8; j++) acc[i][j] = 0.0f;

    for (int k0 = 0; k0 < IN_F; k0 += BK) {
        int gr = row0 + a_row;
        float4 av = make_float4(0.f, 0.f, 0.f, 0.f);
        if (gr < N_NODES)
            av = *(const float4*)(A + (size_t)gr * IN_F + k0 + a_k4);
        As[a_k4 + 0][a_row] = av.x;
        As[a_k4 + 1][a_row] = av.y;
        As[a_k4 + 2][a_row] = av.z;
        As[a_k4 + 3][a_row] = av.w;

        *(float4*)&Bs[b_k][b_n4] =
            *(const float4*)(W + (size_t)(k0 + b_k) * HID + b_n4);
        __syncthreads();

        #pragma unroll
        for (int kk = 0; kk < BK; kk++) {
            float ra[8], rb[8];
            *(float4*)(ra)     = *(float4*)&As[kk][ty * 8];
            *(float4*)(ra + 4) = *(float4*)&As[kk][ty * 8 + 4];
            *(float4*)(rb)     = *(float4*)&Bs[kk][tx * 8];
            *(float4*)(rb + 4) = *(float4*)&Bs[kk][tx * 8 + 4];
            #pragma unroll
            for (int i = 0; i < 8; i++)
                #pragma unroll
                for (int j = 0; j < 8; j++)
                    acc[i][j] = fmaf(ra[i], rb[j], acc[i][j]);
        }
        __syncthreads();
    }

    #pragma unroll
    for (int i = 0; i < 8; i++) {
        int gr = row0 + ty * 8 + i;
        if (gr < N_NODES) {
            float* c = g_h + (size_t)gr * HID + tx * 8;
            *(float4*)(c)     = make_float4(acc[i][0], acc[i][1], acc[i][2], acc[i][3]);
            *(float4*)(c + 4) = make_float4(acc[i][4], acc[i][5], acc[i][6], acc[i][7]);
        }
    }
}

// ---------------- layer-1 self-loop init: a1 = h * dinv^2 -----------------
__global__ void k_init1() {
    int idx = blockIdx.x * blockDim.x + threadIdx.x;   // float4 index
    if (idx >= N_NODES * (HID / 4)) return;
    int node = idx / (HID / 4);
    float di = g_dinv[node];
    float s = di * di;
    float4 v = ((const float4*)g_h)[idx];
    v.x *= s; v.y *= s; v.z *= s; v.w *= s;
    ((float4*)g_a1)[idx] = v;
}

// ---------------- scatter1: warp per edge, 128 feats ----------------------
__global__ void k_scatter1(const int* __restrict__ src, const int* __restrict__ dst, int E) {
    int gid  = blockIdx.x * blockDim.x + threadIdx.x;
    int e    = gid >> 5;
    int lane = gid & 31;
    if (e >= E) return;
    int s = src[e], d = dst[e];
    float nrm = g_dinv[s] * g_dinv[d];
    float4 v = ((const float4*)(g_h + (size_t)s * HID))[lane];
    v.x *= nrm; v.y *= nrm; v.z *= nrm; v.w *= nrm;
    red_add_v4(g_a1 + (size_t)d * HID + lane * 4, v);
}

// ---------------- GEMM2: h2 = relu(a1 + b1) @ W2 --------------------------
__global__ __launch_bounds__(256) void k_gemm2(const float* __restrict__ W2,
                                               const float* __restrict__ b1) {
    __shared__ float W2s[HID * NCLS];
    __shared__ float b1s[HID];
    int tid = threadIdx.x;
    for (int i = tid; i < HID * NCLS; i += 256) W2s[i] = W2[i];
    if (tid < HID) b1s[tid] = b1[tid];
    __syncthreads();

    int r = blockIdx.x * 8 + (tid >> 5);   // warp per row
    int c = tid & 31;
    if (r >= N_NODES) return;

    const float* arow = g_a1 + (size_t)r * HID;
    float acc = 0.0f;
    #pragma unroll 8
    for (int k = 0; k < HID; k++) {
        float a = fmaxf(arow[k] + b1s[k], 0.0f);
        acc = fmaf(a, W2s[k * NCLS + c], acc);
    }
    g_h2[(size_t)r * NCLS + c] = acc;
}

// ---------------- out init: out = h2 * dinv^2 + b2 ------------------------
__global__ void k_init2(const float* __restrict__ b2, float* __restrict__ out) {
    int idx = blockIdx.x * blockDim.x + threadIdx.x;   // float4 index
    if (idx >= N_NODES * (NCLS / 4)) return;
    int node = idx / (NCLS / 4);
    int c4   = idx % (NCLS / 4);
    float di = g_dinv[node];
    float s = di * di;
    float4 v = ((const float4*)g_h2)[idx];
    float4 b = ((const float4*)b2)[c4];
    float4 o = make_float4(v.x * s + b.x, v.y * s + b.y, v.z * s + b.z, v.w * s + b.w);
    ((float4*)out)[idx] = o;
}

// ---------------- scatter2: 8 lanes per edge, 32 feats --------------------
__global__ void k_scatter2(const int* __restrict__ src, const int* __restrict__ dst,
                           int E, float* __restrict__ out) {
    int gid  = blockIdx.x * blockDim.x + threadIdx.x;
    int e    = gid >> 3;
    int part = gid & 7;
    if (e >= E) return;
    int s = src[e], d = dst[e];
    float nrm = g_dinv[s] * g_dinv[d];
    float4 v = ((const float4*)(g_h2 + (size_t)s * NCLS))[part];
    v.x *= nrm; v.y *= nrm; v.z *= nrm; v.w *= nrm;
    red_add_v4(out + (size_t)d * NCLS + part * 4, v);
}

// ---------------- launch ---------------------------------------------------
extern "C" void kernel_launch(void* const* d_in, const int* in_sizes, int n_in,
                              void* d_out, int out_size) {
    const float* x  = (const float*)d_in[0];
    const int*   ei = (const int*)  d_in[1];
    const float* W1 = (const float*)d_in[2];
    const float* b1 = (const float*)d_in[3];
    const float* W2 = (const float*)d_in[4];
    const float* b2 = (const float*)d_in[5];
    float* out = (float*)d_out;

    const int E = in_sizes[1] / 2;
    const int* src = ei;
    const int* dst = ei + E;

    k_deg_init <<<(N_NODES + 255) / 256, 256>>>();
    k_deg_count<<<(E + 255) / 256, 256>>>(dst, E);
    k_dinv     <<<(N_NODES + 255) / 256, 256>>>();

    k_gemm1    <<<(N_NODES + 127) / 128, 256>>>(x, W1);
    k_init1    <<<(N_NODES * (HID / 4) + 255) / 256, 256>>>();

    {
        long long threads = (long long)E * 32;
        k_scatter1<<<(unsigned)((threads + 255) / 256), 256>>>(src, dst, E);
    }

    k_gemm2    <<<(N_NODES + 7) / 8, 256>>>(W2, b1);
    k_init2    <<<(N_NODES * (NCLS / 4) + 255) / 256, 256>>>(b2, out);

    {
        long long threads = (long long)E * 8;
        k_scatter2<<<(unsigned)((threads + 255) / 256), 256>>>(src, dst, E, out);
    }
}

// round 4
// speedup vs baseline: 1.1314x; 1.1314x over previous
#include <cuda_runtime.h>
#include <cstdint>

#define N_NODES 100000
#define IN_F    512
#define HID     128
#define NCLS    32

// ---------------- scratch (static device globals; no allocations) ----------
__device__ __align__(16) float g_dinv[N_NODES];
__device__ __align__(16) float g_h  [(size_t)N_NODES * HID];   // h*dinv  (pre-scaled)
__device__ __align__(16) float g_a1 [(size_t)N_NODES * HID];   // aggregated layer-1 (pre-bias)
__device__ __align__(16) float g_h2 [(size_t)N_NODES * NCLS];  // h2*dinv (pre-scaled)

__device__ __forceinline__ void red_add_v4(float* addr, float4 v) {
    asm volatile("red.global.add.v4.f32 [%0], {%1, %2, %3, %4};"
                 :: "l"(addr), "f"(v.x), "f"(v.y), "f"(v.z), "f"(v.w)
                 : "memory");
}

__device__ __forceinline__ uint32_t f2tf32(float f) {
    uint32_t r;
    asm("cvt.rna.tf32.f32 %0, %1;" : "=r"(r) : "f"(f));
    return r;
}

__device__ __forceinline__ void mma_tf32(float* d, const uint32_t* a, const uint32_t* b) {
    asm volatile(
        "mma.sync.aligned.m16n8k8.row.col.f32.tf32.tf32.f32 "
        "{%0,%1,%2,%3}, {%4,%5,%6,%7}, {%8,%9}, {%0,%1,%2,%3};"
        : "+f"(d[0]), "+f"(d[1]), "+f"(d[2]), "+f"(d[3])
        : "r"(a[0]), "r"(a[1]), "r"(a[2]), "r"(a[3]), "r"(b[0]), "r"(b[1]));
}

// ---------------- degree / dinv -------------------------------------------
__global__ void k_deg_init() {
    int i = blockIdx.x * blockDim.x + threadIdx.x;
    if (i < N_NODES) g_dinv[i] = 1.0f;   // self loop
}

__global__ void k_deg_count(const int* __restrict__ dst, int E) {
    int e = blockIdx.x * blockDim.x + threadIdx.x;
    if (e < E) atomicAdd(&g_dinv[dst[e]], 1.0f);
}

__global__ void k_dinv() {
    int i = blockIdx.x * blockDim.x + threadIdx.x;
    if (i < N_NODES) g_dinv[i] = rsqrtf(g_dinv[i]);
}

// ---------------- GEMM1 (tf32 tensor cores, 3-mma split) -------------------
// h = x @ W1 ;  writes g_h = h*dinv, g_a1 = h*dinv^2
// Block: 256 thr = 8 warps (2x4), tile 128x128x16; warp tile 64x32.
#define AS_STRIDE 20    // [m][k] layout, pad -> conflict-free frag loads
#define BS_STRIDE 136   // [k][n] layout, pad -> conflict-free frag loads

__global__ __launch_bounds__(256, 2) void k_gemm1(const float* __restrict__ A,
                                                  const float* __restrict__ W) {
    __shared__ float As_hi[128][AS_STRIDE];
    __shared__ float As_lo[128][AS_STRIDE];
    __shared__ float Bs_hi[16][BS_STRIDE];
    __shared__ float Bs_lo[16][BS_STRIDE];

    const int tid  = threadIdx.x;
    const int wid  = tid >> 5;
    const int lane = tid & 31;
    const int gid  = lane >> 2;
    const int tig  = lane & 3;
    const int wm   = wid >> 2;   // 0..1
    const int wn   = wid & 3;    // 0..3
    const int row0 = blockIdx.x * 128;

    // staging indices
    const int a_r  = tid >> 1;          // 0..127
    const int a_kq = (tid & 1) * 8;     // 0 or 8
    const int b_k  = tid >> 4;          // 0..15
    const int b_n  = (tid & 15) * 8;    // 0..120

    float acc[4][4][4];
    #pragma unroll
    for (int i = 0; i < 4; i++)
        #pragma unroll
        for (int j = 0; j < 4; j++)
            #pragma unroll
            for (int v = 0; v < 4; v++) acc[i][j][v] = 0.0f;

    const bool a_valid = (row0 + a_r) < N_NODES;
    const float* a_ptr = A + (size_t)(row0 + a_r) * IN_F;

    for (int k0 = 0; k0 < IN_F; k0 += 16) {
        // ---- stage A (hi/lo split; truncation split keeps lo exact) ----
        #pragma unroll
        for (int h = 0; h < 2; h++) {
            int kk = a_kq + h * 4;
            float4 v = a_valid ? *(const float4*)(a_ptr + k0 + kk)
                               : make_float4(0.f, 0.f, 0.f, 0.f);
            float4 hi, lo;
            hi.x = __uint_as_float(__float_as_uint(v.x) & 0xFFFFE000u);
            hi.y = __uint_as_float(__float_as_uint(v.y) & 0xFFFFE000u);
            hi.z = __uint_as_float(__float_as_uint(v.z) & 0xFFFFE000u);
            hi.w = __uint_as_float(__float_as_uint(v.w) & 0xFFFFE000u);
            lo.x = __uint_as_float(f2tf32(v.x - hi.x));
            lo.y = __uint_as_float(f2tf32(v.y - hi.y));
            lo.z = __uint_as_float(f2tf32(v.z - hi.z));
            lo.w = __uint_as_float(f2tf32(v.w - hi.w));
            *(float4*)&As_hi[a_r][kk] = hi;
            *(float4*)&As_lo[a_r][kk] = lo;
        }
        // ---- stage B ----
        #pragma unroll
        for (int h = 0; h < 2; h++) {
            int nn = b_n + h * 4;
            float4 v = *(const float4*)(W + (size_t)(k0 + b_k) * HID + nn);
            float4 hi, lo;
            hi.x = __uint_as_float(__float_as_uint(v.x) & 0xFFFFE000u);
            hi.y = __uint_as_float(__float_as_uint(v.y) & 0xFFFFE000u);
            hi.z = __uint_as_float(__float_as_uint(v.z) & 0xFFFFE000u);
            hi.w = __uint_as_float(__float_as_uint(v.w) & 0xFFFFE000u);
            lo.x = __uint_as_float(f2tf32(v.x - hi.x));
            lo.y = __uint_as_float(f2tf32(v.y - hi.y));
            lo.z = __uint_as_float(f2tf32(v.z - hi.z));
            lo.w = __uint_as_float(f2tf32(v.w - hi.w));
            *(float4*)&Bs_hi[b_k][nn] = hi;
            *(float4*)&Bs_lo[b_k][nn] = lo;
        }
        __syncthreads();

        #pragma unroll
        for (int ks = 0; ks < 2; ks++) {
            const int kb = ks * 8;
            // B fragments: all 4 n-frags, hi+lo
            uint32_t bh[4][2], bl[4][2];
            #pragma unroll
            for (int nf = 0; nf < 4; nf++) {
                int n0 = wn * 32 + nf * 8 + gid;
                bh[nf][0] = __float_as_uint(Bs_hi[kb + tig][n0]);
                bh[nf][1] = __float_as_uint(Bs_hi[kb + tig + 4][n0]);
                bl[nf][0] = __float_as_uint(Bs_lo[kb + tig][n0]);
                bl[nf][1] = __float_as_uint(Bs_lo[kb + tig + 4][n0]);
            }
            #pragma unroll
            for (int mh = 0; mh < 2; mh++) {
                uint32_t ah[2][4], al[2][4];
                #pragma unroll
                for (int mi = 0; mi < 2; mi++) {
                    int m0 = wm * 64 + (mh * 2 + mi) * 16 + gid;
                    ah[mi][0] = __float_as_uint(As_hi[m0][kb + tig]);
                    ah[mi][1] = __float_as_uint(As_hi[m0 + 8][kb + tig]);
                    ah[mi][2] = __float_as_uint(As_hi[m0][kb + tig + 4]);
                    ah[mi][3] = __float_as_uint(As_hi[m0 + 8][kb + tig + 4]);
                    al[mi][0] = __float_as_uint(As_lo[m0][kb + tig]);
                    al[mi][1] = __float_as_uint(As_lo[m0 + 8][kb + tig]);
                    al[mi][2] = __float_as_uint(As_lo[m0][kb + tig + 4]);
                    al[mi][3] = __float_as_uint(As_lo[m0 + 8][kb + tig + 4]);
                }
                #pragma unroll
                for (int mi = 0; mi < 2; mi++)
                    #pragma unroll
                    for (int nf = 0; nf < 4; nf++) {
                        float* d = acc[mh * 2 + mi][nf];
                        mma_tf32(d, ah[mi], bh[nf]);   // hi*hi
                        mma_tf32(d, ah[mi], bl[nf]);   // hi*lo
                        mma_tf32(d, al[mi], bh[nf]);   // lo*hi
                    }
            }
        }
        __syncthreads();
    }

    // ---- epilogue: g_h = h*dinv ; g_a1 = h*dinv^2 ----
    #pragma unroll
    for (int mf = 0; mf < 4; mf++) {
        int ra = row0 + wm * 64 + mf * 16 + gid;
        int rb = ra + 8;
        float da = (ra < N_NODES) ? g_dinv[ra] : 0.0f;
        float db = (rb < N_NODES) ? g_dinv[rb] : 0.0f;
        #pragma unroll
        for (int nf = 0; nf < 4; nf++) {
            int col = wn * 32 + nf * 8 + tig * 2;
            float* d = acc[mf][nf];
            if (ra < N_NODES) {
                float2 hs = make_float2(d[0] * da, d[1] * da);
                *(float2*)(g_h  + (size_t)ra * HID + col) = hs;
                *(float2*)(g_a1 + (size_t)ra * HID + col) =
                    make_float2(hs.x * da, hs.y * da);
            }
            if (rb < N_NODES) {
                float2 hs = make_float2(d[2] * db, d[3] * db);
                *(float2*)(g_h  + (size_t)rb * HID + col) = hs;
                *(float2*)(g_a1 + (size_t)rb * HID + col) =
                    make_float2(hs.x * db, hs.y * db);
            }
        }
    }
}

// ---------------- scatter1: warp per edge, 128 feats ----------------------
// msg = g_h[src] (already h*dinv[src]) * dinv[dst]
__global__ void k_scatter1(const int* __restrict__ src, const int* __restrict__ dst, int E) {
    int gid  = blockIdx.x * blockDim.x + threadIdx.x;
    int e    = gid >> 5;
    int lane = gid & 31;
    if (e >= E) return;
    int s = src[e], d = dst[e];
    float nrm = g_dinv[d];
    float4 v = ((const float4*)(g_h + (size_t)s * HID))[lane];
    v.x *= nrm; v.y *= nrm; v.z *= nrm; v.w *= nrm;
    red_add_v4(g_a1 + (size_t)d * HID + lane * 4, v);
}

// ---------------- GEMM2: h2 = relu(a1 + b1) @ W2 --------------------------
// writes g_h2 = h2*dinv, out = h2*dinv^2 + b2  (init2 fused)
__global__ __launch_bounds__(256) void k_gemm2(const float* __restrict__ W2,
                                               const float* __restrict__ b1,
                                               const float* __restrict__ b2,
                                               float* __restrict__ out) {
    __shared__ float W2s[HID * NCLS];
    __shared__ float b1s[HID];
    int tid = threadIdx.x;
    for (int i = tid; i < HID * NCLS; i += 256) W2s[i] = W2[i];
    if (tid < HID) b1s[tid] = b1[tid];
    __syncthreads();

    int r = blockIdx.x * 8 + (tid >> 5);   // warp per row
    int c = tid & 31;
    if (r >= N_NODES) return;

    const float* arow = g_a1 + (size_t)r * HID;
    float acc = 0.0f;
    #pragma unroll 8
    for (int k = 0; k < HID; k++) {
        float a = fmaxf(arow[k] + b1s[k], 0.0f);
        acc = fmaf(a, W2s[k * NCLS + c], acc);
    }
    float di = g_dinv[r];
    float hs = acc * di;
    g_h2[(size_t)r * NCLS + c] = hs;
    out[(size_t)r * NCLS + c]  = hs * di + b2[c];
}

// ---------------- scatter2: 8 lanes per edge, 32 feats --------------------
__global__ void k_scatter2(const int* __restrict__ src, const int* __restrict__ dst,
                           int E, float* __restrict__ out) {
    int gid  = blockIdx.x * blockDim.x + threadIdx.x;
    int e    = gid >> 3;
    int part = gid & 7;
    if (e >= E) return;
    int s = src[e], d = dst[e];
    float nrm = g_dinv[d];
    float4 v = ((const float4*)(g_h2 + (size_t)s * NCLS))[part];
    v.x *= nrm; v.y *= nrm; v.z *= nrm; v.w *= nrm;
    red_add_v4(out + (size_t)d * NCLS + part * 4, v);
}

// ---------------- launch ---------------------------------------------------
extern "C" void kernel_launch(void* const* d_in, const int* in_sizes, int n_in,
                              void* d_out, int out_size) {
    const float* x  = (const float*)d_in[0];
    const int*   ei = (const int*)  d_in[1];
    const float* W1 = (const float*)d_in[2];
    const float* b1 = (const float*)d_in[3];
    const float* W2 = (const float*)d_in[4];
    const float* b2 = (const float*)d_in[5];
    float* out = (float*)d_out;

    const int E = in_sizes[1] / 2;
    const int* src = ei;
    const int* dst = ei + E;

    k_deg_init <<<(N_NODES + 255) / 256, 256>>>();
    k_deg_count<<<(E + 255) / 256, 256>>>(dst, E);
    k_dinv     <<<(N_NODES + 255) / 256, 256>>>();

    k_gemm1    <<<(N_NODES + 127) / 128, 256>>>(x, W1);

    {
        long long threads = (long long)E * 32;
        k_scatter1<<<(unsigned)((threads + 255) / 256), 256>>>(src, dst, E);
    }

    k_gemm2    <<<(N_NODES + 7) / 8, 256>>>(W2, b1, b2, out);

    {
        long long threads = (long long)E * 8;
        k_scatter2<<<(unsigned)((threads + 255) / 256), 256>>>(src, dst, E, out);
    }
}

// round 7
// speedup vs baseline: 1.2153x; 1.0742x over previous
#include <cuda_runtime.h>
#include <cstdint>

#define N_NODES 100000
#define IN_F    512
#define HID     128
#define NCLS    32

// ---------------- scratch (static device globals; no allocations) ----------
__device__ __align__(16) float g_dinv[N_NODES];
__device__ __align__(16) float g_h  [(size_t)N_NODES * HID];   // h*dinv
__device__ __align__(16) float g_a1 [(size_t)N_NODES * HID];   // aggregated layer-1
__device__ __align__(16) float g_h2 [(size_t)N_NODES * NCLS];  // h2*dinv
__device__ __align__(16) float g_w1_hi[(size_t)IN_F * HID];    // W1 hi (tf32-valued) [k][n]
__device__ __align__(16) float g_w1_lo[(size_t)IN_F * HID];    // W1 lo (tf32-valued) [k][n]

__device__ __forceinline__ void red_add_v4(float* addr, float4 v) {
    asm volatile("red.global.add.v4.f32 [%0], {%1, %2, %3, %4};"
                 :: "l"(addr), "f"(v.x), "f"(v.y), "f"(v.z), "f"(v.w)
                 : "memory");
}

__device__ __forceinline__ uint32_t f2tf32(float f) {
    uint32_t r;
    asm("cvt.rna.tf32.f32 %0, %1;" : "=r"(r) : "f"(f));
    return r;
}

__device__ __forceinline__ void mma_tf32(float* d, const uint32_t* a, const uint32_t* b) {
    asm volatile(
        "mma.sync.aligned.m16n8k8.row.col.f32.tf32.tf32.f32 "
        "{%0,%1,%2,%3}, {%4,%5,%6,%7}, {%8,%9}, {%0,%1,%2,%3};"
        : "+f"(d[0]), "+f"(d[1]), "+f"(d[2]), "+f"(d[3])
        : "r"(a[0]), "r"(a[1]), "r"(a[2]), "r"(a[3]), "r"(b[0]), "r"(b[1]));
}

// ---------------- degree / dinv -------------------------------------------
__global__ void k_deg_init() {
    int i = blockIdx.x * blockDim.x + threadIdx.x;
    if (i < N_NODES) g_dinv[i] = 1.0f;
}
__global__ void k_deg_count(const int* __restrict__ dst, int E) {
    int e = blockIdx.x * blockDim.x + threadIdx.x;
    if (e < E) atomicAdd(&g_dinv[dst[e]], 1.0f);
}
__global__ void k_dinv() {
    int i = blockIdx.x * blockDim.x + threadIdx.x;
    if (i < N_NODES) g_dinv[i] = rsqrtf(g_dinv[i]);
}

// ---------------- W1 tf32 hi/lo pre-split ----------------------------------
__global__ void k_w1split(const float* __restrict__ W1) {
    int idx = blockIdx.x * blockDim.x + threadIdx.x;
    if (idx >= IN_F * HID) return;
    float v = W1[idx];
    float hi = __uint_as_float(__float_as_uint(v) & 0xFFFFE000u);
    g_w1_hi[idx] = hi;
    g_w1_lo[idx] = __uint_as_float(f2tf32(v - hi));
}

// ---------------- GEMM1 (tf32 mma, 3-term split, double-buffered) ----------
// h = x @ W1 ; writes g_h = h*dinv, g_a1 = h*dinv^2
// 256 thr = 8 warps (2x4), block tile 128x128x16; warp tile 64x32.
#define AS_STRIDE 20
#define BS_STRIDE 136
#define NIT (IN_F / 16)
// per-buffer float offsets
#define OFF_AHI 0
#define OFF_ALO 2560                       // 128*20
#define OFF_BHI 5120
#define OFF_BLO 7296                       // +16*136
#define BUF_FLOATS 9472                    // total per buffer
#define SMEM_BYTES (2 * BUF_FLOATS * 4)    // 75776

__global__ __launch_bounds__(256, 2) void k_gemm1(const float* __restrict__ A) {
    extern __shared__ __align__(16) float sm[];

    const int tid  = threadIdx.x;
    const int wid  = tid >> 5;
    const int lane = tid & 31;
    const int gid  = lane >> 2;
    const int tig  = lane & 3;
    const int wm   = wid >> 2;   // 0..1
    const int wn   = wid & 3;    // 0..3
    const int row0 = blockIdx.x * 128;

    const int a_r  = tid >> 1;          // 0..127
    const int a_kq = (tid & 1) * 8;     // 0 or 8
    const int b_k  = tid >> 4;          // 0..15
    const int b_n  = (tid & 15) * 8;    // 0..120

    float acc[4][4][4];
    #pragma unroll
    for (int i = 0; i < 4; i++)
        #pragma unroll
        for (int j = 0; j < 4; j++)
            #pragma unroll
            for (int v = 0; v < 4; v++) acc[i][j][v] = 0.0f;

    const bool a_valid = (row0 + a_r) < N_NODES;
    const float* a_ptr = A + (size_t)(row0 + a_r) * IN_F;

    float4 ar[2], bhr[2], blr[2];

    // ---- prologue: load tile 0 into regs ----
    #pragma unroll
    for (int h = 0; h < 2; h++) {
        ar[h] = a_valid ? *(const float4*)(a_ptr + a_kq + h * 4)
                        : make_float4(0.f, 0.f, 0.f, 0.f);
        bhr[h] = *(const float4*)(g_w1_hi + (size_t)b_k * HID + b_n + h * 4);
        blr[h] = *(const float4*)(g_w1_lo + (size_t)b_k * HID + b_n + h * 4);
    }
    // store tile 0 -> buffer 0
    {
        float* buf = sm;
        #pragma unroll
        for (int h = 0; h < 2; h++) {
            float4 v = ar[h];
            float4 hi, lo;
            hi.x = __uint_as_float(__float_as_uint(v.x) & 0xFFFFE000u);
            hi.y = __uint_as_float(__float_as_uint(v.y) & 0xFFFFE000u);
            hi.z = __uint_as_float(__float_as_uint(v.z) & 0xFFFFE000u);
            hi.w = __uint_as_float(__float_as_uint(v.w) & 0xFFFFE000u);
            lo.x = __uint_as_float(f2tf32(v.x - hi.x));
            lo.y = __uint_as_float(f2tf32(v.y - hi.y));
            lo.z = __uint_as_float(f2tf32(v.z - hi.z));
            lo.w = __uint_as_float(f2tf32(v.w - hi.w));
            int o = a_r * AS_STRIDE + a_kq + h * 4;
            *(float4*)(buf + OFF_AHI + o) = hi;
            *(float4*)(buf + OFF_ALO + o) = lo;
            int ob = b_k * BS_STRIDE + b_n + h * 4;
            *(float4*)(buf + OFF_BHI + ob) = bhr[h];
            *(float4*)(buf + OFF_BLO + ob) = blr[h];
        }
    }
    __syncthreads();

    for (int it = 0; it < NIT; it++) {
        const int b = it & 1;
        const float* buf = sm + b * BUF_FLOATS;
        const bool has_next = (it + 1) < NIT;

        // ---- issue global loads for next tile ----
        if (has_next) {
            const int k0n = (it + 1) * 16;
            #pragma unroll
            for (int h = 0; h < 2; h++) {
                ar[h] = a_valid ? *(const float4*)(a_ptr + k0n + a_kq + h * 4)
                                : make_float4(0.f, 0.f, 0.f, 0.f);
                bhr[h] = *(const float4*)(g_w1_hi + (size_t)(k0n + b_k) * HID + b_n + h * 4);
                blr[h] = *(const float4*)(g_w1_lo + (size_t)(k0n + b_k) * HID + b_n + h * 4);
            }
        }

        // ---- mma on current tile ----
        const float* AsH = buf + OFF_AHI;
        const float* AsL = buf + OFF_ALO;
        const float* BsH = buf + OFF_BHI;
        const float* BsL = buf + OFF_BLO;

        #pragma unroll
        for (int ks = 0; ks < 2; ks++) {
            const int kb = ks * 8;
            uint32_t bh[4][2], bl[4][2];
            #pragma unroll
            for (int nf = 0; nf < 4; nf++) {
                int n0 = wn * 32 + nf * 8 + gid;
                bh[nf][0] = __float_as_uint(BsH[(kb + tig)     * BS_STRIDE + n0]);
                bh[nf][1] = __float_as_uint(BsH[(kb + tig + 4) * BS_STRIDE + n0]);
                bl[nf][0] = __float_as_uint(BsL[(kb + tig)     * BS_STRIDE + n0]);
                bl[nf][1] = __float_as_uint(BsL[(kb + tig + 4) * BS_STRIDE + n0]);
            }
            #pragma unroll
            for (int mh = 0; mh < 2; mh++) {
                uint32_t ah[2][4], al[2][4];
                #pragma unroll
                for (int mi = 0; mi < 2; mi++) {
                    int m0 = wm * 64 + (mh * 2 + mi) * 16 + gid;
                    ah[mi][0] = __float_as_uint(AsH[m0       * AS_STRIDE + kb + tig]);
                    ah[mi][1] = __float_as_uint(AsH[(m0 + 8) * AS_STRIDE + kb + tig]);
                    ah[mi][2] = __float_as_uint(AsH[m0       * AS_STRIDE + kb + tig + 4]);
                    ah[mi][3] = __float_as_uint(AsH[(m0 + 8) * AS_STRIDE + kb + tig + 4]);
                    al[mi][0] = __float_as_uint(AsL[m0       * AS_STRIDE + kb + tig]);
                    al[mi][1] = __float_as_uint(AsL[(m0 + 8) * AS_STRIDE + kb + tig]);
                    al[mi][2] = __float_as_uint(AsL[m0       * AS_STRIDE + kb + tig + 4]);
                    al[mi][3] = __float_as_uint(AsL[(m0 + 8) * AS_STRIDE + kb + tig + 4]);
                }
                #pragma unroll
                for (int mi = 0; mi < 2; mi++)
                    #pragma unroll
                    for (int nf = 0; nf < 4; nf++) {
                        float* d = acc[mh * 2 + mi][nf];
                        mma_tf32(d, ah[mi], bh[nf]);   // hi*hi
                        mma_tf32(d, ah[mi], bl[nf]);   // hi*lo
                        mma_tf32(d, al[mi], bh[nf]);   // lo*hi
                    }
            }
        }

        // ---- convert + store next tile into the other buffer ----
        if (has_next) {
            float* nbuf = sm + (b ^ 1) * BUF_FLOATS;
            #pragma unroll
            for (int h = 0; h < 2; h++) {
                float4 v = ar[h];
                float4 hi, lo;
                hi.x = __uint_as_float(__float_as_uint(v.x) & 0xFFFFE000u);
                hi.y = __uint_as_float(__float_as_uint(v.y) & 0xFFFFE000u);
                hi.z = __uint_as_float(__float_as_uint(v.z) & 0xFFFFE000u);
                hi.w = __uint_as_float(__float_as_uint(v.w) & 0xFFFFE000u);
                lo.x = __uint_as_float(f2tf32(v.x - hi.x));
                lo.y = __uint_as_float(f2tf32(v.y - hi.y));
                lo.z = __uint_as_float(f2tf32(v.z - hi.z));
                lo.w = __uint_as_float(f2tf32(v.w - hi.w));
                int o = a_r * AS_STRIDE + a_kq + h * 4;
                *(float4*)(nbuf + OFF_AHI + o) = hi;
                *(float4*)(nbuf + OFF_ALO + o) = lo;
                int ob = b_k * BS_STRIDE + b_n + h * 4;
                *(float4*)(nbuf + OFF_BHI + ob) = bhr[h];
                *(float4*)(nbuf + OFF_BLO + ob) = blr[h];
            }
        }
        __syncthreads();
    }

    // ---- epilogue: g_h = h*dinv ; g_a1 = h*dinv^2 ----
    #pragma unroll
    for (int mf = 0; mf < 4; mf++) {
        int ra = row0 + wm * 64 + mf * 16 + gid;
        int rb = ra + 8;
        float da = (ra < N_NODES) ? g_dinv[ra] : 0.0f;
        float db = (rb < N_NODES) ? g_dinv[rb] : 0.0f;
        #pragma unroll
        for (int nf = 0; nf < 4; nf++) {
            int col = wn * 32 + nf * 8 + tig * 2;
            float* d = acc[mf][nf];
            if (ra < N_NODES) {
                float2 hs = make_float2(d[0] * da, d[1] * da);
                *(float2*)(g_h  + (size_t)ra * HID + col) = hs;
                *(float2*)(g_a1 + (size_t)ra * HID + col) =
                    make_float2(hs.x * da, hs.y * da);
            }
            if (rb < N_NODES) {
                float2 hs = make_float2(d[2] * db, d[3] * db);
                *(float2*)(g_h  + (size_t)rb * HID + col) = hs;
                *(float2*)(g_a1 + (size_t)rb * HID + col) =
                    make_float2(hs.x * db, hs.y * db);
            }
        }
    }
}

// ---------------- scatter1: warp per edge, 128 feats ----------------------
__global__ void k_scatter1(const int* __restrict__ src, const int* __restrict__ dst, int E) {
    int gid  = blockIdx.x * blockDim.x + threadIdx.x;
    int e    = gid >> 5;
    int lane = gid & 31;
    if (e >= E) return;
    int s = src[e], d = dst[e];
    float nrm = g_dinv[d];
    float4 v = ((const float4*)(g_h + (size_t)s * HID))[lane];
    v.x *= nrm; v.y *= nrm; v.z *= nrm; v.w *= nrm;
    red_add_v4(g_a1 + (size_t)d * HID + lane * 4, v);
}

// ---------------- GEMM2: h2 = relu(a1 + b1) @ W2 --------------------------
// warp per row; coalesced row loads + shuffle broadcast
__global__ __launch_bounds__(256) void k_gemm2(const float* __restrict__ W2,
                                               const float* __restrict__ b1,
                                               const float* __restrict__ b2,
                                               float* __restrict__ out) {
    __shared__ float W2s[HID * NCLS];
    __shared__ float b1s[HID];
    int tid = threadIdx.x;
    for (int i = tid; i < HID * NCLS; i += 256) W2s[i] = W2[i];
    if (tid < HID) b1s[tid] = b1[tid];
    __syncthreads();

    int r = blockIdx.x * 8 + (tid >> 5);
    int c = tid & 31;
    if (r >= N_NODES) return;

    const float* arow = g_a1 + (size_t)r * HID;
    float acc = 0.0f;
    #pragma unroll
    for (int k0 = 0; k0 < HID; k0 += 32) {
        float mine = fmaxf(arow[k0 + c] + b1s[k0 + c], 0.0f);  // coalesced
        #pragma unroll
        for (int j = 0; j < 32; j++) {
            float a = __shfl_sync(0xFFFFFFFFu, mine, j);
            acc = fmaf(a, W2s[(k0 + j) * NCLS + c], acc);
        }
    }
    float di = g_dinv[r];
    float hs = acc * di;
    g_h2[(size_t)r * NCLS + c] = hs;
    out[(size_t)r * NCLS + c]  = hs * di + b2[c];
}

// ---------------- scatter2: 8 lanes per edge, 32 feats --------------------
__global__ void k_scatter2(const int* __restrict__ src, const int* __restrict__ dst,
                           int E, float* __restrict__ out) {
    int gid  = blockIdx.x * blockDim.x + threadIdx.x;
    int e    = gid >> 3;
    int part = gid & 7;
    if (e >= E) return;
    int s = src[e], d = dst[e];
    float nrm = g_dinv[d];
    float4 v = ((const float4*)(g_h2 + (size_t)s * NCLS))[part];
    v.x *= nrm; v.y *= nrm; v.z *= nrm; v.w *= nrm;
    red_add_v4(out + (size_t)d * NCLS + part * 4, v);
}

// ---------------- launch ---------------------------------------------------
extern "C" void kernel_launch(void* const* d_in, const int* in_sizes, int n_in,
                              void* d_out, int out_size) {
    const float* x  = (const float*)d_in[0];
    const int*   ei = (const int*)  d_in[1];
    const float* W1 = (const float*)d_in[2];
    const float* b1 = (const float*)d_in[3];
    const float* W2 = (const float*)d_in[4];
    const float* b2 = (const float*)d_in[5];
    float* out = (float*)d_out;

    const int E = in_sizes[1] / 2;
    const int* src = ei;
    const int* dst = ei + E;

    cudaFuncSetAttribute(k_gemm1, cudaFuncAttributeMaxDynamicSharedMemorySize, SMEM_BYTES);

    k_deg_init <<<(N_NODES + 255) / 256, 256>>>();
    k_deg_count<<<(E + 255) / 256, 256>>>(dst, E);
    k_dinv     <<<(N_NODES + 255) / 256, 256>>>();
    k_w1split  <<<(IN_F * HID + 255) / 256, 256>>>(W1);

    k_gemm1    <<<(N_NODES + 127) / 128, 256, SMEM_BYTES>>>(x);

    {
        long long threads = (long long)E * 32;
        k_scatter1<<<(unsigned)((threads + 255) / 256), 256>>>(src, dst, E);
    }

    k_gemm2    <<<(N_NODES + 7) / 8, 256>>>(W2, b1, b2, out);

    {
        long long threads = (long long)E * 8;
        k_scatter2<<<(unsigned)((threads + 255) / 256), 256>>>(src, dst, E, out);
    }
}

// round 8
// speedup vs baseline: 1.5601x; 1.2837x over previous
#include <cuda_runtime.h>
#include <cstdint>

#define N_NODES 100000
#define IN_F    512
#define HID     128
#define NCLS    32
#define E_MAX   1600000
#define NB_SCAN 98          // ceil(100000/1024)

// ---------------- scratch (static device globals; no allocations) ----------
__device__ __align__(16) float g_dinv[N_NODES];
__device__ __align__(16) float g_h  [(size_t)N_NODES * HID];   // h*dinv
__device__ __align__(16) float g_a1 [(size_t)N_NODES * HID];   // aggregated layer-1
__device__ __align__(16) float g_h2 [(size_t)N_NODES * NCLS];  // h2*dinv
__device__ __align__(16) float g_w1_hi[(size_t)IN_F * HID];
__device__ __align__(16) float g_w1_lo[(size_t)IN_F * HID];
// CSR
__device__ int g_deg[N_NODES];
__device__ int g_rowptr[N_NODES + 1];
__device__ int g_bsums[NB_SCAN];
__device__ int g_tops[NB_SCAN];
__device__ int g_fill[N_NODES];
__device__ int g_adj[E_MAX];

__device__ __forceinline__ uint32_t f2tf32(float f) {
    uint32_t r;
    asm("cvt.rna.tf32.f32 %0, %1;" : "=r"(r) : "f"(f));
    return r;
}

__device__ __forceinline__ void mma_tf32(float* d, const uint32_t* a, const uint32_t* b) {
    asm volatile(
        "mma.sync.aligned.m16n8k8.row.col.f32.tf32.tf32.f32 "
        "{%0,%1,%2,%3}, {%4,%5,%6,%7}, {%8,%9}, {%0,%1,%2,%3};"
        : "+f"(d[0]), "+f"(d[1]), "+f"(d[2]), "+f"(d[3])
        : "r"(a[0]), "r"(a[1]), "r"(a[2]), "r"(a[3]), "r"(b[0]), "r"(b[1]));
}

// ---------------- degree / CSR build ---------------------------------------
__global__ void k_deg_zero() {
    int i = blockIdx.x * blockDim.x + threadIdx.x;
    if (i < N_NODES) g_deg[i] = 0;
}
__global__ void k_deg_count(const int* __restrict__ dst, int E) {
    int e = blockIdx.x * blockDim.x + threadIdx.x;
    if (e < E) atomicAdd(&g_deg[dst[e]], 1);
}
// block-wise inclusive scan -> exclusive within block; block sums out
__global__ __launch_bounds__(1024) void k_scan_block() {
    __shared__ int s[1024];
    int tid = threadIdx.x;
    int i = blockIdx.x * 1024 + tid;
    int v = (i < N_NODES) ? g_deg[i] : 0;
    s[tid] = v;
    __syncthreads();
    #pragma unroll
    for (int off = 1; off < 1024; off <<= 1) {
        int t = (tid >= off) ? s[tid - off] : 0;
        __syncthreads();
        s[tid] += t;
        __syncthreads();
    }
    if (i < N_NODES) g_rowptr[i] = s[tid] - v;   // exclusive, block-local
    if (tid == 1023) g_bsums[blockIdx.x] = s[1023];
}
__global__ void k_scan_tops() {
    if (threadIdx.x == 0) {
        int run = 0;
        for (int b = 0; b < NB_SCAN; b++) {
            g_tops[b] = run;
            run += g_bsums[b];
        }
    }
}
__global__ __launch_bounds__(1024) void k_scan_add(int E) {
    int i = blockIdx.x * 1024 + threadIdx.x;
    if (i < N_NODES) {
        g_rowptr[i] += g_tops[blockIdx.x];
        g_fill[i] = 0;
        g_dinv[i] = rsqrtf((float)(g_deg[i] + 1));   // +1 self loop
    }
    if (i == 0) g_rowptr[N_NODES] = E;
}
__global__ void k_fill(const int* __restrict__ src, const int* __restrict__ dst, int E) {
    int e = blockIdx.x * blockDim.x + threadIdx.x;
    if (e >= E) return;
    int d = dst[e];
    int pos = atomicAdd(&g_fill[d], 1);
    g_adj[g_rowptr[d] + pos] = src[e];
}

// ---------------- W1 tf32 hi/lo pre-split ----------------------------------
__global__ void k_w1split(const float* __restrict__ W1) {
    int idx = blockIdx.x * blockDim.x + threadIdx.x;
    if (idx >= IN_F * HID) return;
    float v = W1[idx];
    float hi = __uint_as_float(__float_as_uint(v) & 0xFFFFE000u);
    g_w1_hi[idx] = hi;
    g_w1_lo[idx] = __uint_as_float(f2tf32(v - hi));
}

// ---------------- GEMM1 (tf32 mma, 3-term split, double-buffered) ----------
// h = x @ W1 ; writes g_h = h*dinv only
#define AS_STRIDE 20
#define BS_STRIDE 136
#define NIT (IN_F / 16)
#define OFF_AHI 0
#define OFF_ALO 2560
#define OFF_BHI 5120
#define OFF_BLO 7296
#define BUF_FLOATS 9472
#define SMEM_BYTES (2 * BUF_FLOATS * 4)

__global__ __launch_bounds__(256, 2) void k_gemm1(const float* __restrict__ A) {
    extern __shared__ __align__(16) float sm[];

    const int tid  = threadIdx.x;
    const int wid  = tid >> 5;
    const int lane = tid & 31;
    const int gid  = lane >> 2;
    const int tig  = lane & 3;
    const int wm   = wid >> 2;
    const int wn   = wid & 3;
    const int row0 = blockIdx.x * 128;

    const int a_r  = tid >> 1;
    const int a_kq = (tid & 1) * 8;
    const int b_k  = tid >> 4;
    const int b_n  = (tid & 15) * 8;

    float acc[4][4][4];
    #pragma unroll
    for (int i = 0; i < 4; i++)
        #pragma unroll
        for (int j = 0; j < 4; j++)
            #pragma unroll
            for (int v = 0; v < 4; v++) acc[i][j][v] = 0.0f;

    const bool a_valid = (row0 + a_r) < N_NODES;
    const float* a_ptr = A + (size_t)(row0 + a_r) * IN_F;

    float4 ar[2], bhr[2], blr[2];

    #pragma unroll
    for (int h = 0; h < 2; h++) {
        ar[h] = a_valid ? *(const float4*)(a_ptr + a_kq + h * 4)
                        : make_float4(0.f, 0.f, 0.f, 0.f);
        bhr[h] = *(const float4*)(g_w1_hi + (size_t)b_k * HID + b_n + h * 4);
        blr[h] = *(const float4*)(g_w1_lo + (size_t)b_k * HID + b_n + h * 4);
    }
    {
        float* buf = sm;
        #pragma unroll
        for (int h = 0; h < 2; h++) {
            float4 v = ar[h];
            float4 hi, lo;
            hi.x = __uint_as_float(__float_as_uint(v.x) & 0xFFFFE000u);
            hi.y = __uint_as_float(__float_as_uint(v.y) & 0xFFFFE000u);
            hi.z = __uint_as_float(__float_as_uint(v.z) & 0xFFFFE000u);
            hi.w = __uint_as_float(__float_as_uint(v.w) & 0xFFFFE000u);
            lo.x = __uint_as_float(f2tf32(v.x - hi.x));
            lo.y = __uint_as_float(f2tf32(v.y - hi.y));
            lo.z = __uint_as_float(f2tf32(v.z - hi.z));
            lo.w = __uint_as_float(f2tf32(v.w - hi.w));
            int o = a_r * AS_STRIDE + a_kq + h * 4;
            *(float4*)(buf + OFF_AHI + o) = hi;
            *(float4*)(buf + OFF_ALO + o) = lo;
            int ob = b_k * BS_STRIDE + b_n + h * 4;
            *(float4*)(buf + OFF_BHI + ob) = bhr[h];
            *(float4*)(buf + OFF_BLO + ob) = blr[h];
        }
    }
    __syncthreads();

    for (int it = 0; it < NIT; it++) {
        const int b = it & 1;
        const float* buf = sm + b * BUF_FLOATS;
        const bool has_next = (it + 1) < NIT;

        if (has_next) {
            const int k0n = (it + 1) * 16;
            #pragma unroll
            for (int h = 0; h < 2; h++) {
                ar[h] = a_valid ? *(const float4*)(a_ptr + k0n + a_kq + h * 4)
                                : make_float4(0.f, 0.f, 0.f, 0.f);
                bhr[h] = *(const float4*)(g_w1_hi + (size_t)(k0n + b_k) * HID + b_n + h * 4);
                blr[h] = *(const float4*)(g_w1_lo + (size_t)(k0n + b_k) * HID + b_n + h * 4);
            }
        }

        const float* AsH = buf + OFF_AHI;
        const float* AsL = buf + OFF_ALO;
        const float* BsH = buf + OFF_BHI;
        const float* BsL = buf + OFF_BLO;

        #pragma unroll
        for (int ks = 0; ks < 2; ks++) {
            const int kb = ks * 8;
            uint32_t bh[4][2], bl[4][2];
            #pragma unroll
            for (int nf = 0; nf < 4; nf++) {
                int n0 = wn * 32 + nf * 8 + gid;
                bh[nf][0] = __float_as_uint(BsH[(kb + tig)     * BS_STRIDE + n0]);
                bh[nf][1] = __float_as_uint(BsH[(kb + tig + 4) * BS_STRIDE + n0]);
                bl[nf][0] = __float_as_uint(BsL[(kb + tig)     * BS_STRIDE + n0]);
                bl[nf][1] = __float_as_uint(BsL[(kb + tig + 4) * BS_STRIDE + n0]);
            }
            #pragma unroll
            for (int mh = 0; mh < 2; mh++) {
                uint32_t ah[2][4], al[2][4];
                #pragma unroll
                for (int mi = 0; mi < 2; mi++) {
                    int m0 = wm * 64 + (mh * 2 + mi) * 16 + gid;
                    ah[mi][0] = __float_as_uint(AsH[m0       * AS_STRIDE + kb + tig]);
                    ah[mi][1] = __float_as_uint(AsH[(m0 + 8) * AS_STRIDE + kb + tig]);
                    ah[mi][2] = __float_as_uint(AsH[m0       * AS_STRIDE + kb + tig + 4]);
                    ah[mi][3] = __float_as_uint(AsH[(m0 + 8) * AS_STRIDE + kb + tig + 4]);
                    al[mi][0] = __float_as_uint(AsL[m0       * AS_STRIDE + kb + tig]);
                    al[mi][1] = __float_as_uint(AsL[(m0 + 8) * AS_STRIDE + kb + tig]);
                    al[mi][2] = __float_as_uint(AsL[m0       * AS_STRIDE + kb + tig + 4]);
                    al[mi][3] = __float_as_uint(AsL[(m0 + 8) * AS_STRIDE + kb + tig + 4]);
                }
                #pragma unroll
                for (int mi = 0; mi < 2; mi++)
                    #pragma unroll
                    for (int nf = 0; nf < 4; nf++) {
                        float* d = acc[mh * 2 + mi][nf];
                        mma_tf32(d, ah[mi], bh[nf]);
                        mma_tf32(d, ah[mi], bl[nf]);
                        mma_tf32(d, al[mi], bh[nf]);
                    }
            }
        }

        if (has_next) {
            float* nbuf = sm + (b ^ 1) * BUF_FLOATS;
            #pragma unroll
            for (int h = 0; h < 2; h++) {
                float4 v = ar[h];
                float4 hi, lo;
                hi.x = __uint_as_float(__float_as_uint(v.x) & 0xFFFFE000u);
                hi.y = __uint_as_float(__float_as_uint(v.y) & 0xFFFFE000u);
                hi.z = __uint_as_float(__float_as_uint(v.z) & 0xFFFFE000u);
                hi.w = __uint_as_float(__float_as_uint(v.w) & 0xFFFFE000u);
                lo.x = __uint_as_float(f2tf32(v.x - hi.x));
                lo.y = __uint_as_float(f2tf32(v.y - hi.y));
                lo.z = __uint_as_float(f2tf32(v.z - hi.z));
                lo.w = __uint_as_float(f2tf32(v.w - hi.w));
                int o = a_r * AS_STRIDE + a_kq + h * 4;
                *(float4*)(nbuf + OFF_AHI + o) = hi;
                *(float4*)(nbuf + OFF_ALO + o) = lo;
                int ob = b_k * BS_STRIDE + b_n + h * 4;
                *(float4*)(nbuf + OFF_BHI + ob) = bhr[h];
                *(float4*)(nbuf + OFF_BLO + ob) = blr[h];
            }
        }
        __syncthreads();
    }

    // ---- epilogue: g_h = h*dinv ----
    #pragma unroll
    for (int mf = 0; mf < 4; mf++) {
        int ra = row0 + wm * 64 + mf * 16 + gid;
        int rb = ra + 8;
        float da = (ra < N_NODES) ? g_dinv[ra] : 0.0f;
        float db = (rb < N_NODES) ? g_dinv[rb] : 0.0f;
        #pragma unroll
        for (int nf = 0; nf < 4; nf++) {
            int col = wn * 32 + nf * 8 + tig * 2;
            float* d = acc[mf][nf];
            if (ra < N_NODES)
                *(float2*)(g_h + (size_t)ra * HID + col) =
                    make_float2(d[0] * da, d[1] * da);
            if (rb < N_NODES)
                *(float2*)(g_h + (size_t)rb * HID + col) =
                    make_float2(d[2] * db, d[3] * db);
        }
    }
}

// ---------------- gather1: warp per dst node, 128 feats --------------------
// a1[d] = dinv[d] * (g_h[d] + sum_{s in adj[d]} g_h[s])
__global__ __launch_bounds__(256) void k_gather1() {
    int node = blockIdx.x * 8 + (threadIdx.x >> 5);
    int lane = threadIdx.x & 31;
    if (node >= N_NODES) return;

    const float4* selfp = (const float4*)(g_h + (size_t)node * HID);
    float4 acc = selfp[lane];

    int beg = g_rowptr[node], end = g_rowptr[node + 1];
    for (int i = beg; i < end; i += 32) {
        int myidx = i + lane;
        int s = (myidx < end) ? g_adj[myidx] : 0;
        int cnt = min(32, end - i);
        for (int j = 0; j < cnt; j++) {
            int sj = __shfl_sync(0xFFFFFFFFu, s, j);
            float4 v = ((const float4*)(g_h + (size_t)sj * HID))[lane];
            acc.x += v.x; acc.y += v.y; acc.z += v.z; acc.w += v.w;
        }
    }
    float di = g_dinv[node];
    acc.x *= di; acc.y *= di; acc.z *= di; acc.w *= di;
    ((float4*)(g_a1 + (size_t)node * HID))[lane] = acc;
}

// ---------------- GEMM2: h2 = relu(a1 + b1) @ W2 ; g_h2 = h2*dinv ----------
__global__ __launch_bounds__(256) void k_gemm2(const float* __restrict__ W2,
                                               const float* __restrict__ b1) {
    __shared__ float W2s[HID * NCLS];
    __shared__ float b1s[HID];
    int tid = threadIdx.x;
    for (int i = tid; i < HID * NCLS; i += 256) W2s[i] = W2[i];
    if (tid < HID) b1s[tid] = b1[tid];
    __syncthreads();

    int r = blockIdx.x * 8 + (tid >> 5);
    int c = tid & 31;
    if (r >= N_NODES) return;

    const float* arow = g_a1 + (size_t)r * HID;
    float acc = 0.0f;
    #pragma unroll
    for (int k0 = 0; k0 < HID; k0 += 32) {
        float mine = fmaxf(arow[k0 + c] + b1s[k0 + c], 0.0f);
        #pragma unroll
        for (int j = 0; j < 32; j++) {
            float a = __shfl_sync(0xFFFFFFFFu, mine, j);
            acc = fmaf(a, W2s[(k0 + j) * NCLS + c], acc);
        }
    }
    g_h2[(size_t)r * NCLS + c] = acc * g_dinv[r];
}

// ---------------- gather2: warp per dst node, 32 feats ---------------------
// out[d] = dinv[d] * (g_h2[d] + sum g_h2[s]) + b2
__global__ __launch_bounds__(256) void k_gather2(const float* __restrict__ b2,
                                                 float* __restrict__ out) {
    int node = blockIdx.x * 8 + (threadIdx.x >> 5);
    int lane = threadIdx.x & 31;
    if (node >= N_NODES) return;

    float acc = g_h2[(size_t)node * NCLS + lane];

    int beg = g_rowptr[node], end = g_rowptr[node + 1];
    for (int i = beg; i < end; i += 32) {
        int myidx = i + lane;
        int s = (myidx < end) ? g_adj[myidx] : 0;
        int cnt = min(32, end - i);
        for (int j = 0; j < cnt; j++) {
            int sj = __shfl_sync(0xFFFFFFFFu, s, j);
            acc += g_h2[(size_t)sj * NCLS + lane];
        }
    }
    out[(size_t)node * NCLS + lane] = acc * g_dinv[node] + b2[lane];
}

// ---------------- launch ---------------------------------------------------
extern "C" void kernel_launch(void* const* d_in, const int* in_sizes, int n_in,
                              void* d_out, int out_size) {
    const float* x  = (const float*)d_in[0];
    const int*   ei = (const int*)  d_in[1];
    const float* W1 = (const float*)d_in[2];
    const float* b1 = (const float*)d_in[3];
    const float* W2 = (const float*)d_in[4];
    const float* b2 = (const float*)d_in[5];
    float* out = (float*)d_out;

    const int E = in_sizes[1] / 2;
    const int* src = ei;
    const int* dst = ei + E;

    cudaFuncSetAttribute(k_gemm1, cudaFuncAttributeMaxDynamicSharedMemorySize, SMEM_BYTES);

    // CSR build + dinv
    k_deg_zero  <<<(N_NODES + 255) / 256, 256>>>();
    k_deg_count <<<(E + 255) / 256, 256>>>(dst, E);
    k_scan_block<<<NB_SCAN, 1024>>>();
    k_scan_tops <<<1, 32>>>();
    k_scan_add  <<<NB_SCAN, 1024>>>(E);
    k_fill      <<<(E + 255) / 256, 256>>>(src, dst, E);

    k_w1split   <<<(IN_F * HID + 255) / 256, 256>>>(W1);
    k_gemm1     <<<(N_NODES + 127) / 128, 256, SMEM_BYTES>>>(x);

    k_gather1   <<<(N_NODES + 7) / 8, 256>>>();
    k_gemm2     <<<(N_NODES + 7) / 8, 256>>>(W2, b1);
    k_gather2   <<<(N_NODES + 7) / 8, 256>>>(b2, out);
}

// round 9
// speedup vs baseline: 1.7921x; 1.1487x over previous
#include <cuda_runtime.h>
#include <cuda_bf16.h>
#include <cstdint>

#define N_NODES 100000
#define IN_F    512
#define HID     128
#define NCLS    32
#define E_MAX   1600000
#define NB_SCAN 98          // ceil(100000/1024)

// ---------------- scratch (static device globals; no allocations) ----------
__device__ __align__(16) float g_dinv[N_NODES];
__device__ __align__(16) float g_h  [(size_t)N_NODES * HID];   // h*dinv
__device__ __align__(16) float g_a1 [(size_t)N_NODES * HID];   // aggregated layer-1
__device__ __align__(16) float g_h2 [(size_t)N_NODES * NCLS];  // h2*dinv
// W1^T packed bf16x2: [n][kpair] (kpair = 2 consecutive k, low half = even k)
__device__ __align__(16) uint32_t g_w1t_hi[(size_t)HID * (IN_F / 2)];
__device__ __align__(16) uint32_t g_w1t_lo[(size_t)HID * (IN_F / 2)];
// CSR
__device__ int g_deg[N_NODES];
__device__ int g_rowptr[N_NODES + 1];
__device__ int g_bsums[NB_SCAN];
__device__ int g_tops[NB_SCAN];
__device__ int g_fill[N_NODES];
__device__ int g_adj[E_MAX];

// ---------------- helpers ---------------------------------------------------
__device__ __forceinline__ uint32_t smem_u32(const void* p) {
    uint32_t a;
    asm("{ .reg .u64 t; cvta.to.shared.u64 t, %1; cvt.u32.u64 %0, t; }"
        : "=r"(a) : "l"(p));
    return a;
}

__device__ __forceinline__ void ldsm_x4(uint32_t* r, uint32_t addr) {
    asm volatile("ldmatrix.sync.aligned.m8n8.x4.shared.b16 {%0,%1,%2,%3}, [%4];"
        : "=r"(r[0]), "=r"(r[1]), "=r"(r[2]), "=r"(r[3]) : "r"(addr));
}
__device__ __forceinline__ void ldsm_x2(uint32_t* r, uint32_t addr) {
    asm volatile("ldmatrix.sync.aligned.m8n8.x2.shared.b16 {%0,%1}, [%2];"
        : "=r"(r[0]), "=r"(r[1]) : "r"(addr));
}

__device__ __forceinline__ void mma_bf16(float* d, const uint32_t* a, const uint32_t* b) {
    asm volatile(
        "mma.sync.aligned.m16n8k16.row.col.f32.bf16.bf16.f32 "
        "{%0,%1,%2,%3}, {%4,%5,%6,%7}, {%8,%9}, {%0,%1,%2,%3};"
        : "+f"(d[0]), "+f"(d[1]), "+f"(d[2]), "+f"(d[3])
        : "r"(a[0]), "r"(a[1]), "r"(a[2]), "r"(a[3]), "r"(b[0]), "r"(b[1]));
}

__device__ __forceinline__ uint32_t pack_bf2(__nv_bfloat16 a, __nv_bfloat16 b) {
    return (uint32_t)__bfloat16_as_ushort(a) |
           ((uint32_t)__bfloat16_as_ushort(b) << 16);
}

// ---------------- degree / CSR build ---------------------------------------
__global__ void k_deg_zero() {
    int i = blockIdx.x * blockDim.x + threadIdx.x;
    if (i < N_NODES) g_deg[i] = 0;
}
__global__ void k_deg_count(const int* __restrict__ dst, int E) {
    int e = blockIdx.x * blockDim.x + threadIdx.x;
    if (e < E) atomicAdd(&g_deg[dst[e]], 1);
}
__global__ __launch_bounds__(1024) void k_scan_block() {
    __shared__ int s[1024];
    int tid = threadIdx.x;
    int i = blockIdx.x * 1024 + tid;
    int v = (i < N_NODES) ? g_deg[i] : 0;
    s[tid] = v;
    __syncthreads();
    #pragma unroll
    for (int off = 1; off < 1024; off <<= 1) {
        int t = (tid >= off) ? s[tid - off] : 0;
        __syncthreads();
        s[tid] += t;
        __syncthreads();
    }
    if (i < N_NODES) g_rowptr[i] = s[tid] - v;
    if (tid == 1023) g_bsums[blockIdx.x] = s[1023];
}
__global__ __launch_bounds__(128) void k_scan_tops() {
    __shared__ int s[128];
    int t = threadIdx.x;
    int v = (t < NB_SCAN) ? g_bsums[t] : 0;
    s[t] = v;
    __syncthreads();
    #pragma unroll
    for (int off = 1; off < 128; off <<= 1) {
        int u = (t >= off) ? s[t - off] : 0;
        __syncthreads();
        s[t] += u;
        __syncthreads();
    }
    if (t < NB_SCAN) g_tops[t] = s[t] - v;   // exclusive
}
__global__ __launch_bounds__(1024) void k_scan_add(int E) {
    int i = blockIdx.x * 1024 + threadIdx.x;
    if (i < N_NODES) {
        g_rowptr[i] += g_tops[blockIdx.x];
        g_fill[i] = 0;
        g_dinv[i] = rsqrtf((float)(g_deg[i] + 1));
    }
    if (i == 0) g_rowptr[N_NODES] = E;
}
__global__ void k_fill(const int* __restrict__ src, const int* __restrict__ dst, int E) {
    int e = blockIdx.x * blockDim.x + threadIdx.x;
    if (e >= E) return;
    int d = dst[e];
    int pos = atomicAdd(&g_fill[d], 1);
    g_adj[g_rowptr[d] + pos] = src[e];
}

// ---------------- W1 transpose + bf16 hi/lo split --------------------------
__global__ void k_w1t(const float* __restrict__ W1) {
    int idx = blockIdx.x * blockDim.x + threadIdx.x;   // HID * IN_F/2
    if (idx >= HID * (IN_F / 2)) return;
    int n  = idx >> 8;        // IN_F/2 = 256 kpairs
    int kp = idx & 255;
    float v0 = W1[(size_t)(2 * kp)     * HID + n];
    float v1 = W1[(size_t)(2 * kp + 1) * HID + n];
    __nv_bfloat16 h0 = __float2bfloat16_rn(v0);
    __nv_bfloat16 h1 = __float2bfloat16_rn(v1);
    __nv_bfloat16 l0 = __float2bfloat16_rn(v0 - __bfloat162float(h0));
    __nv_bfloat16 l1 = __float2bfloat16_rn(v1 - __bfloat162float(h1));
    g_w1t_hi[idx] = pack_bf2(h0, h1);
    g_w1t_lo[idx] = pack_bf2(l0, l1);
}

// ---------------- GEMM1 (bf16 mma m16n8k16, 3-term split, ldmatrix) --------
// h = x @ W1 ; writes g_h = h*dinv
// 256 thr = 8 warps (2m x 4n), block tile 128x128x32; warp tile 64x32.
#define ASTR 20                     // uint32 stride per row (16 kpairs + pad)
#define NIT  (IN_F / 32)            // 16
#define OFF_AHI 0
#define OFF_ALO 2560
#define OFF_BHI 5120
#define OFF_BLO 7680
#define BUF_U32 10240
#define SMEM_BYTES (2 * BUF_U32 * 4)   // 81920

__global__ __launch_bounds__(256) void k_gemm1(const float* __restrict__ A) {
    extern __shared__ __align__(16) uint32_t sm[];
    const uint32_t sbase = smem_u32(sm);

    const int tid  = threadIdx.x;
    const int wid  = tid >> 5;
    const int lane = tid & 31;
    const int gid  = lane >> 2;
    const int tig  = lane & 3;
    const int wm   = wid >> 2;   // 0..1
    const int wn   = wid & 3;    // 0..3
    const int row0 = blockIdx.x * 128;

    // staging indices: A row = tid>>1, 16 k at (tid&1)*16; B n = tid>>1, 8 kpairs
    const int st_r  = tid >> 1;
    const int st_kp = (tid & 1) * 8;    // kpair offset 0 or 8

    // ldmatrix per-lane address components
    const int lm_a_row = lane & 15;
    const int lm_a_kb  = ((lane >> 4) & 1) * 4;
    const int lm_b_row = lane & 7;
    const int lm_b_kb  = ((lane >> 3) & 1) * 4;

    float acc[4][4][4];
    #pragma unroll
    for (int i = 0; i < 4; i++)
        #pragma unroll
        for (int j = 0; j < 4; j++)
            #pragma unroll
            for (int v = 0; v < 4; v++) acc[i][j][v] = 0.0f;

    const bool a_valid = (row0 + st_r) < N_NODES;
    const float* a_ptr = A + (size_t)(row0 + st_r) * IN_F + st_kp * 2;
    const uint32_t* bhi_ptr = g_w1t_hi + (size_t)st_r * (IN_F / 2) + st_kp;
    const uint32_t* blo_ptr = g_w1t_lo + (size_t)st_r * (IN_F / 2) + st_kp;

    float4 ar[4];
    uint4  bhr[2], blr[2];

    // ---- prologue: load tile 0 ----
    #pragma unroll
    for (int q = 0; q < 4; q++)
        ar[q] = a_valid ? *(const float4*)(a_ptr + q * 4)
                        : make_float4(0.f, 0.f, 0.f, 0.f);
    bhr[0] = *(const uint4*)(bhi_ptr);
    bhr[1] = *(const uint4*)(bhi_ptr + 4);
    blr[0] = *(const uint4*)(blo_ptr);
    blr[1] = *(const uint4*)(blo_ptr + 4);

    // stage tile 0 -> buffer 0
    {
        uint32_t* buf = sm;
        uint4 hi0, hi1, lo0, lo1;
        {
            __nv_bfloat16 h[8], l[8];
            const float* f = (const float*)ar;
            #pragma unroll
            for (int q = 0; q < 8; q++) {
                float va = f[2 * q], vb = f[2 * q + 1];
                __nv_bfloat16 ha = __float2bfloat16_rn(va);
                __nv_bfloat16 hb = __float2bfloat16_rn(vb);
                h[q] = ha; l[q] = hb;  // reuse arrays: store packed below
                uint32_t ph = pack_bf2(ha, hb);
                uint32_t pl = pack_bf2(__float2bfloat16_rn(va - __bfloat162float(ha)),
                                       __float2bfloat16_rn(vb - __bfloat162float(hb)));
                ((uint32_t*)&hi0)[q & 3] = (q < 4) ? ph : ((uint32_t*)&hi0)[q & 3];
                if (q < 4) { ((uint32_t*)&hi0)[q] = ph; ((uint32_t*)&lo0)[q] = pl; }
                else       { ((uint32_t*)&hi1)[q - 4] = ph; ((uint32_t*)&lo1)[q - 4] = pl; }
            }
        }
        int o = st_r * ASTR + st_kp;
        *(uint4*)(buf + OFF_AHI + o)     = hi0;
        *(uint4*)(buf + OFF_AHI + o + 4) = hi1;
        *(uint4*)(buf + OFF_ALO + o)     = lo0;
        *(uint4*)(buf + OFF_ALO + o + 4) = lo1;
        *(uint4*)(buf + OFF_BHI + o)     = bhr[0];
        *(uint4*)(buf + OFF_BHI + o + 4) = bhr[1];
        *(uint4*)(buf + OFF_BLO + o)     = blr[0];
        *(uint4*)(buf + OFF_BLO + o + 4) = blr[1];
    }
    __syncthreads();

    for (int it = 0; it < NIT; it++) {
        const int b = it & 1;
        const uint32_t bufb = sbase + b * (BUF_U32 * 4);
        const bool has_next = (it + 1) < NIT;

        // ---- issue global loads for next tile ----
        if (has_next) {
            const int koff = (it + 1) * 32;
            #pragma unroll
            for (int q = 0; q < 4; q++)
                ar[q] = a_valid ? *(const float4*)(a_ptr + koff + q * 4)
                                : make_float4(0.f, 0.f, 0.f, 0.f);
            bhr[0] = *(const uint4*)(bhi_ptr + koff / 2);
            bhr[1] = *(const uint4*)(bhi_ptr + koff / 2 + 4);
            blr[0] = *(const uint4*)(blo_ptr + koff / 2);
            blr[1] = *(const uint4*)(blo_ptr + koff / 2 + 4);
        }

        // ---- mma on current tile: 2 k-steps of K=16 ----
        #pragma unroll
        for (int ks = 0; ks < 2; ks++) {
            const int kb = ks * 8;
            uint32_t bh[4][2], bl[4][2];
            #pragma unroll
            for (int nf = 0; nf < 4; nf++) {
                int n0 = wn * 32 + nf * 8;
                uint32_t ob = (uint32_t)((n0 + lm_b_row) * ASTR + kb + lm_b_kb) * 4;
                ldsm_x2(bh[nf], bufb + OFF_BHI * 4 + ob);
                ldsm_x2(bl[nf], bufb + OFF_BLO * 4 + ob);
            }
            #pragma unroll
            for (int mf = 0; mf < 4; mf++) {
                int m0 = wm * 64 + mf * 16;
                uint32_t oa = (uint32_t)((m0 + lm_a_row) * ASTR + kb + lm_a_kb) * 4;
                uint32_t ah[4], al[4];
                ldsm_x4(ah, bufb + OFF_AHI * 4 + oa);
                ldsm_x4(al, bufb + OFF_ALO * 4 + oa);
                #pragma unroll
                for (int nf = 0; nf < 4; nf++) {
                    float* d = acc[mf][nf];
                    mma_bf16(d, ah, bh[nf]);   // hi*hi
                    mma_bf16(d, ah, bl[nf]);   // hi*lo
                    mma_bf16(d, al, bh[nf]);   // lo*hi
                }
            }
        }

        // ---- convert + store next tile into other buffer ----
        if (has_next) {
            uint32_t* nbuf = sm + (b ^ 1) * BUF_U32;
            uint4 hi0, hi1, lo0, lo1;
            const float* f = (const float*)ar;
            #pragma unroll
            for (int q = 0; q < 8; q++) {
                float va = f[2 * q], vb = f[2 * q + 1];
                __nv_bfloat16 ha = __float2bfloat16_rn(va);
                __nv_bfloat16 hb = __float2bfloat16_rn(vb);
                uint32_t ph = pack_bf2(ha, hb);
                uint32_t pl = pack_bf2(__float2bfloat16_rn(va - __bfloat162float(ha)),
                                       __float2bfloat16_rn(vb - __bfloat162float(hb)));
                if (q < 4) { ((uint32_t*)&hi0)[q] = ph; ((uint32_t*)&lo0)[q] = pl; }
                else       { ((uint32_t*)&hi1)[q - 4] = ph; ((uint32_t*)&lo1)[q - 4] = pl; }
            }
            int o = st_r * ASTR + st_kp;
            *(uint4*)(nbuf + OFF_AHI + o)     = hi0;
            *(uint4*)(nbuf + OFF_AHI + o + 4) = hi1;
            *(uint4*)(nbuf + OFF_ALO + o)     = lo0;
            *(uint4*)(nbuf + OFF_ALO + o + 4) = lo1;
            *(uint4*)(nbuf + OFF_BHI + o)     = bhr[0];
            *(uint4*)(nbuf + OFF_BHI + o + 4) = bhr[1];
            *(uint4*)(nbuf + OFF_BLO + o)     = blr[0];
            *(uint4*)(nbuf + OFF_BLO + o + 4) = blr[1];
        }
        __syncthreads();
    }

    // ---- epilogue: g_h = h*dinv ----
    #pragma unroll
    for (int mf = 0; mf < 4; mf++) {
        int ra = row0 + wm * 64 + mf * 16 + gid;
        int rb = ra + 8;
        float da = (ra < N_NODES) ? g_dinv[ra] : 0.0f;
        float db = (rb < N_NODES) ? g_dinv[rb] : 0.0f;
        #pragma unroll
        for (int nf = 0; nf < 4; nf++) {
            int col = wn * 32 + nf * 8 + tig * 2;
            float* d = acc[mf][nf];
            if (ra < N_NODES)
                *(float2*)(g_h + (size_t)ra * HID + col) =
                    make_float2(d[0] * da, d[1] * da);
            if (rb < N_NODES)
                *(float2*)(g_h + (size_t)rb * HID + col) =
                    make_float2(d[2] * db, d[3] * db);
        }
    }
}

// ---------------- gather1: warp per dst node, 128 feats --------------------
__global__ __launch_bounds__(256) void k_gather1() {
    int node = blockIdx.x * 8 + (threadIdx.x >> 5);
    int lane = threadIdx.x & 31;
    if (node >= N_NODES) return;

    float4 acc = ((const float4*)(g_h + (size_t)node * HID))[lane];

    int beg = g_rowptr[node], end = g_rowptr[node + 1];
    for (int i = beg; i < end; i += 32) {
        int myidx = i + lane;
        int s = (myidx < end) ? g_adj[myidx] : 0;
        int cnt = min(32, end - i);
        int j = 0;
        for (; j + 4 <= cnt; j += 4) {
            int s0 = __shfl_sync(0xFFFFFFFFu, s, j);
            int s1 = __shfl_sync(0xFFFFFFFFu, s, j + 1);
            int s2 = __shfl_sync(0xFFFFFFFFu, s, j + 2);
            int s3 = __shfl_sync(0xFFFFFFFFu, s, j + 3);
            float4 v0 = ((const float4*)(g_h + (size_t)s0 * HID))[lane];
            float4 v1 = ((const float4*)(g_h + (size_t)s1 * HID))[lane];
            float4 v2 = ((const float4*)(g_h + (size_t)s2 * HID))[lane];
            float4 v3 = ((const float4*)(g_h + (size_t)s3 * HID))[lane];
            acc.x += v0.x + v1.x + v2.x + v3.x;
            acc.y += v0.y + v1.y + v2.y + v3.y;
            acc.z += v0.z + v1.z + v2.z + v3.z;
            acc.w += v0.w + v1.w + v2.w + v3.w;
        }
        for (; j < cnt; j++) {
            int sj = __shfl_sync(0xFFFFFFFFu, s, j);
            float4 v = ((const float4*)(g_h + (size_t)sj * HID))[lane];
            acc.x += v.x; acc.y += v.y; acc.z += v.z; acc.w += v.w;
        }
    }
    float di = g_dinv[node];
    acc.x *= di; acc.y *= di; acc.z *= di; acc.w *= di;
    ((float4*)(g_a1 + (size_t)node * HID))[lane] = acc;
}

// ---------------- GEMM2: h2 = relu(a1 + b1) @ W2 ; g_h2 = h2*dinv ----------
__global__ __launch_bounds__(256) void k_gemm2(const float* __restrict__ W2,
                                               const float* __restrict__ b1) {
    __shared__ float W2s[HID * NCLS];
    __shared__ float b1s[HID];
    int tid = threadIdx.x;
    for (int i = tid; i < HID * NCLS; i += 256) W2s[i] = W2[i];
    if (tid < HID) b1s[tid] = b1[tid];
    __syncthreads();

    int r = blockIdx.x * 8 + (tid >> 5);
    int c = tid & 31;
    if (r >= N_NODES) return;

    const float* arow = g_a1 + (size_t)r * HID;
    float acc = 0.0f;
    #pragma unroll
    for (int k0 = 0; k0 < HID; k0 += 32) {
        float mine = fmaxf(arow[k0 + c] + b1s[k0 + c], 0.0f);
        #pragma unroll
        for (int j = 0; j < 32; j++) {
            float a = __shfl_sync(0xFFFFFFFFu, mine, j);
            acc = fmaf(a, W2s[(k0 + j) * NCLS + c], acc);
        }
    }
    g_h2[(size_t)r * NCLS + c] = acc * g_dinv[r];
}

// ---------------- gather2: warp per dst node, 32 feats ---------------------
__global__ __launch_bounds__(256) void k_gather2(const float* __restrict__ b2,
                                                 float* __restrict__ out) {
    int node = blockIdx.x * 8 + (threadIdx.x >> 5);
    int lane = threadIdx.x & 31;
    if (node >= N_NODES) return;

    float acc = g_h2[(size_t)node * NCLS + lane];

    int beg = g_rowptr[node], end = g_rowptr[node + 1];
    for (int i = beg; i < end; i += 32) {
        int myidx = i + lane;
        int s = (myidx < end) ? g_adj[myidx] : 0;
        int cnt = min(32, end - i);
        int j = 0;
        for (; j + 4 <= cnt; j += 4) {
            int s0 = __shfl_sync(0xFFFFFFFFu, s, j);
            int s1 = __shfl_sync(0xFFFFFFFFu, s, j + 1);
            int s2 = __shfl_sync(0xFFFFFFFFu, s, j + 2);
            int s3 = __shfl_sync(0xFFFFFFFFu, s, j + 3);
            acc += g_h2[(size_t)s0 * NCLS + lane] + g_h2[(size_t)s1 * NCLS + lane]
                 + g_h2[(size_t)s2 * NCLS + lane] + g_h2[(size_t)s3 * NCLS + lane];
        }
        for (; j < cnt; j++) {
            int sj = __shfl_sync(0xFFFFFFFFu, s, j);
            acc += g_h2[(size_t)sj * NCLS + lane];
        }
    }
    out[(size_t)node * NCLS + lane] = acc * g_dinv[node] + b2[lane];
}

// ---------------- launch ---------------------------------------------------
extern "C" void kernel_launch(void* const* d_in, const int* in_sizes, int n_in,
                              void* d_out, int out_size) {
    const float* x  = (const float*)d_in[0];
    const int*   ei = (const int*)  d_in[1];
    const float* W1 = (const float*)d_in[2];
    const float* b1 = (const float*)d_in[3];
    const float* W2 = (const float*)d_in[4];
    const float* b2 = (const float*)d_in[5];
    float* out = (float*)d_out;

    const int E = in_sizes[1] / 2;
    const int* src = ei;
    const int* dst = ei + E;

    cudaFuncSetAttribute(k_gemm1, cudaFuncAttributeMaxDynamicSharedMemorySize, SMEM_BYTES);

    k_deg_zero  <<<(N_NODES + 255) / 256, 256>>>();
    k_deg_count <<<(E + 255) / 256, 256>>>(dst, E);
    k_scan_block<<<NB_SCAN, 1024>>>();
    k_scan_tops <<<1, 128>>>();
    k_scan_add  <<<NB_SCAN, 1024>>>(E);
    k_fill      <<<(E + 255) / 256, 256>>>(src, dst, E);

    k_w1t       <<<(HID * (IN_F / 2) + 255) / 256, 256>>>(W1);
    k_gemm1     <<<(N_NODES + 127) / 128, 256, SMEM_BYTES>>>(x);

    k_gather1   <<<(N_NODES + 7) / 8, 256>>>();
    k_gemm2     <<<(N_NODES + 7) / 8, 256>>>(W2, b1);
    k_gather2   <<<(N_NODES + 7) / 8, 256>>>(b2, out);
}

// round 12
// speedup vs baseline: 1.9386x; 1.0818x over previous
#include <cuda_runtime.h>
#include <cuda_bf16.h>
#include <cstdint>

#define N_NODES 100000
#define IN_F    512
#define HID     128
#define NCLS    32
#define E_MAX   1600000
#define NB_SCAN 98          // ceil(100000/1024)

// ---------------- scratch (static device globals; no allocations) ----------
__device__ __align__(16) float g_dinv[N_NODES];
__device__ __align__(16) float g_h  [(size_t)N_NODES * HID];   // h*dinv
__device__ __align__(16) float g_h2 [(size_t)N_NODES * NCLS];  // h2*dinv
// W1^T packed bf16x2: [n][kpair] (kpair = 2 consecutive k, low half = even k)
__device__ __align__(16) uint32_t g_w1t_hi[(size_t)HID * (IN_F / 2)];
__device__ __align__(16) uint32_t g_w1t_lo[(size_t)HID * (IN_F / 2)];
// CSR
__device__ int g_deg[N_NODES];
__device__ int g_rowptr[N_NODES + 1];
__device__ int g_bsums[NB_SCAN];
__device__ int g_tops[NB_SCAN];
__device__ int g_fill[N_NODES];
__device__ int g_adj[E_MAX];

// ---------------- helpers ---------------------------------------------------
__device__ __forceinline__ uint32_t smem_u32(const void* p) {
    uint32_t a;
    asm("{ .reg .u64 t; cvta.to.shared.u64 t, %1; cvt.u32.u64 %0, t; }"
        : "=r"(a) : "l"(p));
    return a;
}

__device__ __forceinline__ void ldsm_x4(uint32_t* r, uint32_t addr) {
    asm volatile("ldmatrix.sync.aligned.m8n8.x4.shared.b16 {%0,%1,%2,%3}, [%4];"
        : "=r"(r[0]), "=r"(r[1]), "=r"(r[2]), "=r"(r[3]) : "r"(addr));
}
__device__ __forceinline__ void ldsm_x2(uint32_t* r, uint32_t addr) {
    asm volatile("ldmatrix.sync.aligned.m8n8.x2.shared.b16 {%0,%1}, [%2];"
        : "=r"(r[0]), "=r"(r[1]) : "r"(addr));
}

__device__ __forceinline__ void mma_bf16(float* d, const uint32_t* a, const uint32_t* b) {
    asm volatile(
        "mma.sync.aligned.m16n8k16.row.col.f32.bf16.bf16.f32 "
        "{%0,%1,%2,%3}, {%4,%5,%6,%7}, {%8,%9}, {%0,%1,%2,%3};"
        : "+f"(d[0]), "+f"(d[1]), "+f"(d[2]), "+f"(d[3])
        : "r"(a[0]), "r"(a[1]), "r"(a[2]), "r"(a[3]), "r"(b[0]), "r"(b[1]));
}

__device__ __forceinline__ uint32_t pack_bf2(__nv_bfloat16 a, __nv_bfloat16 b) {
    return (uint32_t)__bfloat16_as_ushort(a) |
           ((uint32_t)__bfloat16_as_ushort(b) << 16);
}

// ---------------- degree / CSR build ---------------------------------------
__global__ void k_deg_zero() {
    int i = blockIdx.x * blockDim.x + threadIdx.x;
    if (i < N_NODES) g_deg[i] = 0;
}
__global__ void k_deg_count(const int* __restrict__ dst, int E) {
    int e = blockIdx.x * blockDim.x + threadIdx.x;
    if (e < E) atomicAdd(&g_deg[dst[e]], 1);
}
__global__ __launch_bounds__(1024) void k_scan_block() {
    __shared__ int s[1024];
    int tid = threadIdx.x;
    int i = blockIdx.x * 1024 + tid;
    int v = (i < N_NODES) ? g_deg[i] : 0;
    s[tid] = v;
    __syncthreads();
    #pragma unroll
    for (int off = 1; off < 1024; off <<= 1) {
        int t = (tid >= off) ? s[tid - off] : 0;
        __syncthreads();
        s[tid] += t;
        __syncthreads();
    }
    if (i < N_NODES) g_rowptr[i] = s[tid] - v;
    if (tid == 1023) g_bsums[blockIdx.x] = s[1023];
}
__global__ __launch_bounds__(128) void k_scan_tops() {
    __shared__ int s[128];
    int t = threadIdx.x;
    int v = (t < NB_SCAN) ? g_bsums[t] : 0;
    s[t] = v;
    __syncthreads();
    #pragma unroll
    for (int off = 1; off < 128; off <<= 1) {
        int u = (t >= off) ? s[t - off] : 0;
        __syncthreads();
        s[t] += u;
        __syncthreads();
    }
    if (t < NB_SCAN) g_tops[t] = s[t] - v;   // exclusive
}
__global__ __launch_bounds__(1024) void k_scan_add(int E) {
    int i = blockIdx.x * 1024 + threadIdx.x;
    if (i < N_NODES) {
        g_rowptr[i] += g_tops[blockIdx.x];
        g_fill[i] = 0;
        g_dinv[i] = rsqrtf((float)(g_deg[i] + 1));
    }
    if (i == 0) g_rowptr[N_NODES] = E;
}
__global__ void k_fill(const int* __restrict__ src, const int* __restrict__ dst, int E) {
    int e = blockIdx.x * blockDim.x + threadIdx.x;
    if (e >= E) return;
    int d = dst[e];
    int pos = atomicAdd(&g_fill[d], 1);
    g_adj[g_rowptr[d] + pos] = src[e];
}

// ---------------- W1 transpose + bf16 hi/lo split --------------------------
__global__ void k_w1t(const float* __restrict__ W1) {
    int idx = blockIdx.x * blockDim.x + threadIdx.x;   // HID * IN_F/2
    if (idx >= HID * (IN_F / 2)) return;
    int n  = idx >> 8;        // IN_F/2 = 256 kpairs
    int kp = idx & 255;
    float v0 = W1[(size_t)(2 * kp)     * HID + n];
    float v1 = W1[(size_t)(2 * kp + 1) * HID + n];
    __nv_bfloat16 h0 = __float2bfloat16_rn(v0);
    __nv_bfloat16 h1 = __float2bfloat16_rn(v1);
    __nv_bfloat16 l0 = __float2bfloat16_rn(v0 - __bfloat162float(h0));
    __nv_bfloat16 l1 = __float2bfloat16_rn(v1 - __bfloat162float(h1));
    g_w1t_hi[idx] = pack_bf2(h0, h1);
    g_w1t_lo[idx] = pack_bf2(l0, l1);
}

// ---------------- GEMM1 (bf16 mma m16n8k16, 3-term split, ldmatrix) --------
// h = x @ W1 ; writes g_h = h*dinv
#define ASTR 20
#define NIT  (IN_F / 32)
#define OFF_AHI 0
#define OFF_ALO 2560
#define OFF_BHI 5120
#define OFF_BLO 7680
#define BUF_U32 10240
#define SMEM_BYTES (2 * BUF_U32 * 4)   // 81920

__global__ __launch_bounds__(256) void k_gemm1(const float* __restrict__ A) {
    extern __shared__ __align__(16) uint32_t sm[];
    const uint32_t sbase = smem_u32(sm);

    const int tid  = threadIdx.x;
    const int wid  = tid >> 5;
    const int lane = tid & 31;
    const int gid  = lane >> 2;
    const int tig  = lane & 3;
    const int wm   = wid >> 2;
    const int wn   = wid & 3;
    const int row0 = blockIdx.x * 128;

    const int st_r  = tid >> 1;
    const int st_kp = (tid & 1) * 8;

    const int lm_a_row = lane & 15;
    const int lm_a_kb  = ((lane >> 4) & 1) * 4;
    const int lm_b_row = lane & 7;
    const int lm_b_kb  = ((lane >> 3) & 1) * 4;

    float acc[4][4][4];
    #pragma unroll
    for (int i = 0; i < 4; i++)
        #pragma unroll
        for (int j = 0; j < 4; j++)
            #pragma unroll
            for (int v = 0; v < 4; v++) acc[i][j][v] = 0.0f;

    const bool a_valid = (row0 + st_r) < N_NODES;
    const float* a_ptr = A + (size_t)(row0 + st_r) * IN_F + st_kp * 2;
    const uint32_t* bhi_ptr = g_w1t_hi + (size_t)st_r * (IN_F / 2) + st_kp;
    const uint32_t* blo_ptr = g_w1t_lo + (size_t)st_r * (IN_F / 2) + st_kp;

    float4 ar[4];
    uint4  bhr[2], blr[2];

    #pragma unroll
    for (int q = 0; q < 4; q++)
        ar[q] = a_valid ? *(const float4*)(a_ptr + q * 4)
                        : make_float4(0.f, 0.f, 0.f, 0.f);
    bhr[0] = *(const uint4*)(bhi_ptr);
    bhr[1] = *(const uint4*)(bhi_ptr + 4);
    blr[0] = *(const uint4*)(blo_ptr);
    blr[1] = *(const uint4*)(blo_ptr + 4);

    {
        uint32_t* buf = sm;
        uint4 hi0, hi1, lo0, lo1;
        const float* f = (const float*)ar;
        #pragma unroll
        for (int q = 0; q < 8; q++) {
            float va = f[2 * q], vb = f[2 * q + 1];
            __nv_bfloat16 ha = __float2bfloat16_rn(va);
            __nv_bfloat16 hb = __float2bfloat16_rn(vb);
            uint32_t ph = pack_bf2(ha, hb);
            uint32_t pl = pack_bf2(__float2bfloat16_rn(va - __bfloat162float(ha)),
                                   __float2bfloat16_rn(vb - __bfloat162float(hb)));
            if (q < 4) { ((uint32_t*)&hi0)[q] = ph; ((uint32_t*)&lo0)[q] = pl; }
            else       { ((uint32_t*)&hi1)[q - 4] = ph; ((uint32_t*)&lo1)[q - 4] = pl; }
        }
        int o = st_r * ASTR + st_kp;
        *(uint4*)(buf + OFF_AHI + o)     = hi0;
        *(uint4*)(buf + OFF_AHI + o + 4) = hi1;
        *(uint4*)(buf + OFF_ALO + o)     = lo0;
        *(uint4*)(buf + OFF_ALO + o + 4) = lo1;
        *(uint4*)(buf + OFF_BHI + o)     = bhr[0];
        *(uint4*)(buf + OFF_BHI + o + 4) = bhr[1];
        *(uint4*)(buf + OFF_BLO + o)     = blr[0];
        *(uint4*)(buf + OFF_BLO + o + 4) = blr[1];
    }
    __syncthreads();

    for (int it = 0; it < NIT; it++) {
        const int b = it & 1;
        const uint32_t bufb = sbase + b * (BUF_U32 * 4);
        const bool has_next = (it + 1) < NIT;

        if (has_next) {
            const int koff = (it + 1) * 32;
            #pragma unroll
            for (int q = 0; q < 4; q++)
                ar[q] = a_valid ? *(const float4*)(a_ptr + koff + q * 4)
                                : make_float4(0.f, 0.f, 0.f, 0.f);
            bhr[0] = *(const uint4*)(bhi_ptr + koff / 2);
            bhr[1] = *(const uint4*)(bhi_ptr + koff / 2 + 4);
            blr[0] = *(const uint4*)(blo_ptr + koff / 2);
            blr[1] = *(const uint4*)(blo_ptr + koff / 2 + 4);
        }

        #pragma unroll
        for (int ks = 0; ks < 2; ks++) {
            const int kb = ks * 8;
            uint32_t bh[4][2], bl[4][2];
            #pragma unroll
            for (int nf = 0; nf < 4; nf++) {
                int n0 = wn * 32 + nf * 8;
                uint32_t ob = (uint32_t)((n0 + lm_b_row) * ASTR + kb + lm_b_kb) * 4;
                ldsm_x2(bh[nf], bufb + OFF_BHI * 4 + ob);
                ldsm_x2(bl[nf], bufb + OFF_BLO * 4 + ob);
            }
            #pragma unroll
            for (int mf = 0; mf < 4; mf++) {
                int m0 = wm * 64 + mf * 16;
                uint32_t oa = (uint32_t)((m0 + lm_a_row) * ASTR + kb + lm_a_kb) * 4;
                uint32_t ah[4], al[4];
                ldsm_x4(ah, bufb + OFF_AHI * 4 + oa);
                ldsm_x4(al, bufb + OFF_ALO * 4 + oa);
                #pragma unroll
                for (int nf = 0; nf < 4; nf++) {
                    float* d = acc[mf][nf];
                    mma_bf16(d, ah, bh[nf]);
                    mma_bf16(d, ah, bl[nf]);
                    mma_bf16(d, al, bh[nf]);
                }
            }
        }

        if (has_next) {
            uint32_t* nbuf = sm + (b ^ 1) * BUF_U32;
            uint4 hi0, hi1, lo0, lo1;
            const float* f = (const float*)ar;
            #pragma unroll
            for (int q = 0; q < 8; q++) {
                float va = f[2 * q], vb = f[2 * q + 1];
                __nv_bfloat16 ha = __float2bfloat16_rn(va);
                __nv_bfloat16 hb = __float2bfloat16_rn(vb);
                uint32_t ph = pack_bf2(ha, hb);
                uint32_t pl = pack_bf2(__float2bfloat16_rn(va - __bfloat162float(ha)),
                                       __float2bfloat16_rn(vb - __bfloat162float(hb)));
                if (q < 4) { ((uint32_t*)&hi0)[q] = ph; ((uint32_t*)&lo0)[q] = pl; }
                else       { ((uint32_t*)&hi1)[q - 4] = ph; ((uint32_t*)&lo1)[q - 4] = pl; }
            }
            int o = st_r * ASTR + st_kp;
            *(uint4*)(nbuf + OFF_AHI + o)     = hi0;
            *(uint4*)(nbuf + OFF_AHI + o + 4) = hi1;
            *(uint4*)(nbuf + OFF_ALO + o)     = lo0;
            *(uint4*)(nbuf + OFF_ALO + o + 4) = lo1;
            *(uint4*)(nbuf + OFF_BHI + o)     = bhr[0];
            *(uint4*)(nbuf + OFF_BHI + o + 4) = bhr[1];
            *(uint4*)(nbuf + OFF_BLO + o)     = blr[0];
            *(uint4*)(nbuf + OFF_BLO + o + 4) = blr[1];
        }
        __syncthreads();
    }

    #pragma unroll
    for (int mf = 0; mf < 4; mf++) {
        int ra = row0 + wm * 64 + mf * 16 + gid;
        int rb = ra + 8;
        float da = (ra < N_NODES) ? g_dinv[ra] : 0.0f;
        float db = (rb < N_NODES) ? g_dinv[rb] : 0.0f;
        #pragma unroll
        for (int nf = 0; nf < 4; nf++) {
            int col = wn * 32 + nf * 8 + tig * 2;
            float* d = acc[mf][nf];
            if (ra < N_NODES)
                *(float2*)(g_h + (size_t)ra * HID + col) =
                    make_float2(d[0] * da, d[1] * da);
            if (rb < N_NODES)
                *(float2*)(g_h + (size_t)rb * HID + col) =
                    make_float2(d[2] * db, d[3] * db);
        }
    }
}

// ---------------- fused gather1 + gemm2: warp per dst node -----------------
// agg = dinv[d]*(g_h[d] + sum g_h[s]);  a = relu(agg + b1)
// g_h2[d] = (a @ W2) * dinv[d]
__global__ __launch_bounds__(256) void k_agg_gemm2(const float* __restrict__ W2,
                                                   const float* __restrict__ b1) {
    __shared__ float W2s[HID * NCLS];
    __shared__ float b1s[HID];
    __shared__ float rows[8][HID];
    int tid = threadIdx.x;
    for (int i = tid; i < HID * NCLS; i += 256) W2s[i] = W2[i];
    if (tid < HID) b1s[tid] = b1[tid];
    __syncthreads();

    int w    = tid >> 5;
    int node = blockIdx.x * 8 + w;
    int lane = tid & 31;
    if (node >= N_NODES) return;

    // ---- gather phase ----
    float4 acc = ((const float4*)(g_h + (size_t)node * HID))[lane];

    int beg = g_rowptr[node], end = g_rowptr[node + 1];
    for (int i = beg; i < end; i += 32) {
        int myidx = i + lane;
        int s = (myidx < end) ? g_adj[myidx] : 0;
        int cnt = min(32, end - i);
        int j = 0;
        for (; j + 4 <= cnt; j += 4) {
            int s0 = __shfl_sync(0xFFFFFFFFu, s, j);
            int s1 = __shfl_sync(0xFFFFFFFFu, s, j + 1);
            int s2 = __shfl_sync(0xFFFFFFFFu, s, j + 2);
            int s3 = __shfl_sync(0xFFFFFFFFu, s, j + 3);
            float4 v0 = ((const float4*)(g_h + (size_t)s0 * HID))[lane];
            float4 v1 = ((const float4*)(g_h + (size_t)s1 * HID))[lane];
            float4 v2 = ((const float4*)(g_h + (size_t)s2 * HID))[lane];
            float4 v3 = ((const float4*)(g_h + (size_t)s3 * HID))[lane];
            acc.x += v0.x + v1.x + v2.x + v3.x;
            acc.y += v0.y + v1.y + v2.y + v3.y;
            acc.z += v0.z + v1.z + v2.z + v3.z;
            acc.w += v0.w + v1.w + v2.w + v3.w;
        }
        for (; j < cnt; j++) {
            int sj = __shfl_sync(0xFFFFFFFFu, s, j);
            float4 v = ((const float4*)(g_h + (size_t)sj * HID))[lane];
            acc.x += v.x; acc.y += v.y; acc.z += v.z; acc.w += v.w;
        }
    }
    float di = g_dinv[node];
    // a = relu(agg*dinv + b1), staged to smem row
    {
        const float4 bb = ((const float4*)b1s)[lane];
        float4 a;
        a.x = fmaxf(acc.x * di + bb.x, 0.0f);
        a.y = fmaxf(acc.y * di + bb.y, 0.0f);
        a.z = fmaxf(acc.z * di + bb.z, 0.0f);
        a.w = fmaxf(acc.w * di + bb.w, 0.0f);
        ((float4*)rows[w])[lane] = a;
    }
    __syncwarp();

    // ---- gemm2 phase: out col = lane ----
    float acc2 = 0.0f;
    const float* rw = rows[w];
    #pragma unroll 16
    for (int k = 0; k < HID; k++)
        acc2 = fmaf(rw[k], W2s[k * NCLS + lane], acc2);

    g_h2[(size_t)node * NCLS + lane] = acc2 * di;
}

// ---------------- gather2: warp per dst node, 32 feats ---------------------
__global__ __launch_bounds__(256) void k_gather2(const float* __restrict__ b2,
                                                 float* __restrict__ out) {
    int node = blockIdx.x * 8 + (threadIdx.x >> 5);
    int lane = threadIdx.x & 31;
    if (node >= N_NODES) return;

    float acc = g_h2[(size_t)node * NCLS + lane];

    int beg = g_rowptr[node], end = g_rowptr[node + 1];
    for (int i = beg; i < end; i += 32) {
        int myidx = i + lane;
        int s = (myidx < end) ? g_adj[myidx] : 0;
        int cnt = min(32, end - i);
        int j = 0;
        for (; j + 4 <= cnt; j += 4) {
            int s0 = __shfl_sync(0xFFFFFFFFu, s, j);
            int s1 = __shfl_sync(0xFFFFFFFFu, s, j + 1);
            int s2 = __shfl_sync(0xFFFFFFFFu, s, j + 2);
            int s3 = __shfl_sync(0xFFFFFFFFu, s, j + 3);
            acc += g_h2[(size_t)s0 * NCLS + lane] + g_h2[(size_t)s1 * NCLS + lane]
                 + g_h2[(size_t)s2 * NCLS + lane] + g_h2[(size_t)s3 * NCLS + lane];
        }
        for (; j < cnt; j++) {
            int sj = __shfl_sync(0xFFFFFFFFu, s, j);
            acc += g_h2[(size_t)sj * NCLS + lane];
        }
    }
    out[(size_t)node * NCLS + lane] = acc * g_dinv[node] + b2[lane];
}

// ---------------- launch ---------------------------------------------------
extern "C" void kernel_launch(void* const* d_in, const int* in_sizes, int n_in,
                              void* d_out, int out_size) {
    const float* x  = (const float*)d_in[0];
    const int*   ei = (const int*)  d_in[1];
    const float* W1 = (const float*)d_in[2];
    const float* b1 = (const float*)d_in[3];
    const float* W2 = (const float*)d_in[4];
    const float* b2 = (const float*)d_in[5];
    float* out = (float*)d_out;

    const int E = in_sizes[1] / 2;
    const int* src = ei;
    const int* dst = ei + E;

    cudaFuncSetAttribute(k_gemm1, cudaFuncAttributeMaxDynamicSharedMemorySize, SMEM_BYTES);

    k_deg_zero  <<<(N_NODES + 255) / 256, 256>>>();
    k_deg_count <<<(E + 255) / 256, 256>>>(dst, E);
    k_scan_block<<<NB_SCAN, 1024>>>();
    k_scan_tops <<<1, 128>>>();
    k_scan_add  <<<NB_SCAN, 1024>>>(E);
    k_fill      <<<(E + 255) / 256, 256>>>(src, dst, E);

    k_w1t       <<<(HID * (IN_F / 2) + 255) / 256, 256>>>(W1);
    k_gemm1     <<<(N_NODES + 127) / 128, 256, SMEM_BYTES>>>(x);

    k_agg_gemm2 <<<(N_NODES + 7) / 8, 256>>>(W2, b1);
    k_gather2   <<<(N_NODES + 7) / 8, 256>>>(b2, out);
}

// round 13
// speedup vs baseline: 2.1291x; 1.0983x over previous
#include <cuda_runtime.h>
#include <cuda_bf16.h>
#include <cstdint>

#define N_NODES 100000
#define IN_F    512
#define HID     128
#define NCLS    32
#define E_MAX   1600000
#define NB_SCAN 98          // ceil(100000/1024)

// ---------------- scratch (static device globals; no allocations) ----------
__device__ __align__(16) float g_dinv[N_NODES];
__device__ __align__(16) float g_h  [(size_t)N_NODES * HID];   // raw h (x @ W1)
__device__ __align__(16) float g_h2 [(size_t)N_NODES * NCLS];  // h2*dinv
// W1^T packed bf16x2: [n][kpair]
__device__ __align__(16) uint32_t g_w1t_hi[(size_t)HID * (IN_F / 2)];
__device__ __align__(16) uint32_t g_w1t_lo[(size_t)HID * (IN_F / 2)];
// CSR
__device__ int g_deg[N_NODES];
__device__ int g_rowptr[N_NODES + 1];
__device__ int g_bsums[NB_SCAN];
__device__ int g_tops[NB_SCAN];
__device__ int g_fill[N_NODES];
__device__ int g_adj[E_MAX];

// ---------------- helpers ---------------------------------------------------
__device__ __forceinline__ uint32_t smem_u32(const void* p) {
    uint32_t a;
    asm("{ .reg .u64 t; cvta.to.shared.u64 t, %1; cvt.u32.u64 %0, t; }"
        : "=r"(a) : "l"(p));
    return a;
}

__device__ __forceinline__ void ldsm_x4(uint32_t* r, uint32_t addr) {
    asm volatile("ldmatrix.sync.aligned.m8n8.x4.shared.b16 {%0,%1,%2,%3}, [%4];"
        : "=r"(r[0]), "=r"(r[1]), "=r"(r[2]), "=r"(r[3]) : "r"(addr));
}
__device__ __forceinline__ void ldsm_x2(uint32_t* r, uint32_t addr) {
    asm volatile("ldmatrix.sync.aligned.m8n8.x2.shared.b16 {%0,%1}, [%2];"
        : "=r"(r[0]), "=r"(r[1]) : "r"(addr));
}

__device__ __forceinline__ void mma_bf16(float* d, const uint32_t* a, const uint32_t* b) {
    asm volatile(
        "mma.sync.aligned.m16n8k16.row.col.f32.bf16.bf16.f32 "
        "{%0,%1,%2,%3}, {%4,%5,%6,%7}, {%8,%9}, {%0,%1,%2,%3};"
        : "+f"(d[0]), "+f"(d[1]), "+f"(d[2]), "+f"(d[3])
        : "r"(a[0]), "r"(a[1]), "r"(a[2]), "r"(a[3]), "r"(b[0]), "r"(b[1]));
}

__device__ __forceinline__ uint32_t pack_bf2(__nv_bfloat16 a, __nv_bfloat16 b) {
    return (uint32_t)__bfloat16_as_ushort(a) |
           ((uint32_t)__bfloat16_as_ushort(b) << 16);
}

// ---------------- degree / CSR build ---------------------------------------
__global__ void k_deg_zero() {
    int i = blockIdx.x * blockDim.x + threadIdx.x;
    if (i < N_NODES) g_deg[i] = 0;
}
__global__ void k_deg_count(const int* __restrict__ dst, int E) {
    int e = blockIdx.x * blockDim.x + threadIdx.x;
    if (e < E) atomicAdd(&g_deg[dst[e]], 1);
}
__global__ __launch_bounds__(1024) void k_scan_block() {
    __shared__ int s[1024];
    int tid = threadIdx.x;
    int i = blockIdx.x * 1024 + tid;
    int v = (i < N_NODES) ? g_deg[i] : 0;
    s[tid] = v;
    __syncthreads();
    #pragma unroll
    for (int off = 1; off < 1024; off <<= 1) {
        int t = (tid >= off) ? s[tid - off] : 0;
        __syncthreads();
        s[tid] += t;
        __syncthreads();
    }
    if (i < N_NODES) g_rowptr[i] = s[tid] - v;
    if (tid == 1023) g_bsums[blockIdx.x] = s[1023];
}
__global__ __launch_bounds__(128) void k_scan_tops() {
    __shared__ int s[128];
    int t = threadIdx.x;
    int v = (t < NB_SCAN) ? g_bsums[t] : 0;
    s[t] = v;
    __syncthreads();
    #pragma unroll
    for (int off = 1; off < 128; off <<= 1) {
        int u = (t >= off) ? s[t - off] : 0;
        __syncthreads();
        s[t] += u;
        __syncthreads();
    }
    if (t < NB_SCAN) g_tops[t] = s[t] - v;   // exclusive
}
__global__ __launch_bounds__(1024) void k_scan_add(int E) {
    int i = blockIdx.x * 1024 + threadIdx.x;
    if (i < N_NODES) {
        g_rowptr[i] += g_tops[blockIdx.x];
        g_fill[i] = 0;
        g_dinv[i] = rsqrtf((float)(g_deg[i] + 1));
    }
    if (i == 0) g_rowptr[N_NODES] = E;
}
__global__ void k_fill(const int* __restrict__ src, const int* __restrict__ dst, int E) {
    int e = blockIdx.x * blockDim.x + threadIdx.x;
    if (e >= E) return;
    int d = dst[e];
    int pos = atomicAdd(&g_fill[d], 1);
    g_adj[g_rowptr[d] + pos] = src[e];
}

// ---------------- W1 transpose + bf16 hi/lo split --------------------------
__global__ void k_w1t(const float* __restrict__ W1) {
    int idx = blockIdx.x * blockDim.x + threadIdx.x;
    if (idx >= HID * (IN_F / 2)) return;
    int n  = idx >> 8;
    int kp = idx & 255;
    float v0 = W1[(size_t)(2 * kp)     * HID + n];
    float v1 = W1[(size_t)(2 * kp + 1) * HID + n];
    __nv_bfloat16 h0 = __float2bfloat16_rn(v0);
    __nv_bfloat16 h1 = __float2bfloat16_rn(v1);
    __nv_bfloat16 l0 = __float2bfloat16_rn(v0 - __bfloat162float(h0));
    __nv_bfloat16 l1 = __float2bfloat16_rn(v1 - __bfloat162float(h1));
    g_w1t_hi[idx] = pack_bf2(h0, h1);
    g_w1t_lo[idx] = pack_bf2(l0, l1);
}

// ---------------- GEMM1 (bf16 mma m16n8k16, 3-term split, ldmatrix) --------
// writes RAW h (no dinv) -> no dependency on CSR chain
#define ASTR 20
#define NIT  (IN_F / 32)
#define OFF_AHI 0
#define OFF_ALO 2560
#define OFF_BHI 5120
#define OFF_BLO 7680
#define BUF_U32 10240
#define SMEM_BYTES (2 * BUF_U32 * 4)   // 81920

__global__ __launch_bounds__(256, 2) void k_gemm1(const float* __restrict__ A) {
    extern __shared__ __align__(16) uint32_t sm[];
    const uint32_t sbase = smem_u32(sm);

    const int tid  = threadIdx.x;
    const int wid  = tid >> 5;
    const int lane = tid & 31;
    const int gid  = lane >> 2;
    const int tig  = lane & 3;
    const int wm   = wid >> 2;
    const int wn   = wid & 3;
    const int row0 = blockIdx.x * 128;

    const int st_r  = tid >> 1;
    const int st_kp = (tid & 1) * 8;

    const int lm_a_row = lane & 15;
    const int lm_a_kb  = ((lane >> 4) & 1) * 4;
    const int lm_b_row = lane & 7;
    const int lm_b_kb  = ((lane >> 3) & 1) * 4;

    float acc[4][4][4];
    #pragma unroll
    for (int i = 0; i < 4; i++)
        #pragma unroll
        for (int j = 0; j < 4; j++)
            #pragma unroll
            for (int v = 0; v < 4; v++) acc[i][j][v] = 0.0f;

    const bool a_valid = (row0 + st_r) < N_NODES;
    const float* a_ptr = A + (size_t)(row0 + st_r) * IN_F + st_kp * 2;
    const uint32_t* bhi_ptr = g_w1t_hi + (size_t)st_r * (IN_F / 2) + st_kp;
    const uint32_t* blo_ptr = g_w1t_lo + (size_t)st_r * (IN_F / 2) + st_kp;

    float4 ar[4];
    uint4  bhr[2], blr[2];

    #pragma unroll
    for (int q = 0; q < 4; q++)
        ar[q] = a_valid ? *(const float4*)(a_ptr + q * 4)
                        : make_float4(0.f, 0.f, 0.f, 0.f);
    bhr[0] = *(const uint4*)(bhi_ptr);
    bhr[1] = *(const uint4*)(bhi_ptr + 4);
    blr[0] = *(const uint4*)(blo_ptr);
    blr[1] = *(const uint4*)(blo_ptr + 4);

    {
        uint32_t* buf = sm;
        uint4 hi0, hi1, lo0, lo1;
        const float* f = (const float*)ar;
        #pragma unroll
        for (int q = 0; q < 8; q++) {
            float va = f[2 * q], vb = f[2 * q + 1];
            __nv_bfloat16 ha = __float2bfloat16_rn(va);
            __nv_bfloat16 hb = __float2bfloat16_rn(vb);
            uint32_t ph = pack_bf2(ha, hb);
            uint32_t pl = pack_bf2(__float2bfloat16_rn(va - __bfloat162float(ha)),
                                   __float2bfloat16_rn(vb - __bfloat162float(hb)));
            if (q < 4) { ((uint32_t*)&hi0)[q] = ph; ((uint32_t*)&lo0)[q] = pl; }
            else       { ((uint32_t*)&hi1)[q - 4] = ph; ((uint32_t*)&lo1)[q - 4] = pl; }
        }
        int o = st_r * ASTR + st_kp;
        *(uint4*)(buf + OFF_AHI + o)     = hi0;
        *(uint4*)(buf + OFF_AHI + o + 4) = hi1;
        *(uint4*)(buf + OFF_ALO + o)     = lo0;
        *(uint4*)(buf + OFF_ALO + o + 4) = lo1;
        *(uint4*)(buf + OFF_BHI + o)     = bhr[0];
        *(uint4*)(buf + OFF_BHI + o + 4) = bhr[1];
        *(uint4*)(buf + OFF_BLO + o)     = blr[0];
        *(uint4*)(buf + OFF_BLO + o + 4) = blr[1];
    }
    __syncthreads();

    for (int it = 0; it < NIT; it++) {
        const int b = it & 1;
        const uint32_t bufb = sbase + b * (BUF_U32 * 4);
        const bool has_next = (it + 1) < NIT;

        if (has_next) {
            const int koff = (it + 1) * 32;
            #pragma unroll
            for (int q = 0; q < 4; q++)
                ar[q] = a_valid ? *(const float4*)(a_ptr + koff + q * 4)
                                : make_float4(0.f, 0.f, 0.f, 0.f);
            bhr[0] = *(const uint4*)(bhi_ptr + koff / 2);
            bhr[1] = *(const uint4*)(bhi_ptr + koff / 2 + 4);
            blr[0] = *(const uint4*)(blo_ptr + koff / 2);
            blr[1] = *(const uint4*)(blo_ptr + koff / 2 + 4);
        }

        #pragma unroll
        for (int ks = 0; ks < 2; ks++) {
            const int kb = ks * 8;
            uint32_t bh[4][2], bl[4][2];
            #pragma unroll
            for (int nf = 0; nf < 4; nf++) {
                int n0 = wn * 32 + nf * 8;
                uint32_t ob = (uint32_t)((n0 + lm_b_row) * ASTR + kb + lm_b_kb) * 4;
                ldsm_x2(bh[nf], bufb + OFF_BHI * 4 + ob);
                ldsm_x2(bl[nf], bufb + OFF_BLO * 4 + ob);
            }
            #pragma unroll
            for (int mf = 0; mf < 4; mf++) {
                int m0 = wm * 64 + mf * 16;
                uint32_t oa = (uint32_t)((m0 + lm_a_row) * ASTR + kb + lm_a_kb) * 4;
                uint32_t ah[4], al[4];
                ldsm_x4(ah, bufb + OFF_AHI * 4 + oa);
                ldsm_x4(al, bufb + OFF_ALO * 4 + oa);
                #pragma unroll
                for (int nf = 0; nf < 4; nf++) {
                    float* d = acc[mf][nf];
                    mma_bf16(d, ah, bh[nf]);
                    mma_bf16(d, ah, bl[nf]);
                    mma_bf16(d, al, bh[nf]);
                }
            }
        }

        if (has_next) {
            uint32_t* nbuf = sm + (b ^ 1) * BUF_U32;
            uint4 hi0, hi1, lo0, lo1;
            const float* f = (const float*)ar;
            #pragma unroll
            for (int q = 0; q < 8; q++) {
                float va = f[2 * q], vb = f[2 * q + 1];
                __nv_bfloat16 ha = __float2bfloat16_rn(va);
                __nv_bfloat16 hb = __float2bfloat16_rn(vb);
                uint32_t ph = pack_bf2(ha, hb);
                uint32_t pl = pack_bf2(__float2bfloat16_rn(va - __bfloat162float(ha)),
                                       __float2bfloat16_rn(vb - __bfloat162float(hb)));
                if (q < 4) { ((uint32_t*)&hi0)[q] = ph; ((uint32_t*)&lo0)[q] = pl; }
                else       { ((uint32_t*)&hi1)[q - 4] = ph; ((uint32_t*)&lo1)[q - 4] = pl; }
            }
            int o = st_r * ASTR + st_kp;
            *(uint4*)(nbuf + OFF_AHI + o)     = hi0;
            *(uint4*)(nbuf + OFF_AHI + o + 4) = hi1;
            *(uint4*)(nbuf + OFF_ALO + o)     = lo0;
            *(uint4*)(nbuf + OFF_ALO + o + 4) = lo1;
            *(uint4*)(nbuf + OFF_BHI + o)     = bhr[0];
            *(uint4*)(nbuf + OFF_BHI + o + 4) = bhr[1];
            *(uint4*)(nbuf + OFF_BLO + o)     = blr[0];
            *(uint4*)(nbuf + OFF_BLO + o + 4) = blr[1];
        }
        __syncthreads();
    }

    // ---- epilogue: raw h ----
    #pragma unroll
    for (int mf = 0; mf < 4; mf++) {
        int ra = row0 + wm * 64 + mf * 16 + gid;
        int rb = ra + 8;
        #pragma unroll
        for (int nf = 0; nf < 4; nf++) {
            int col = wn * 32 + nf * 8 + tig * 2;
            float* d = acc[mf][nf];
            if (ra < N_NODES)
                *(float2*)(g_h + (size_t)ra * HID + col) = make_float2(d[0], d[1]);
            if (rb < N_NODES)
                *(float2*)(g_h + (size_t)rb * HID + col) = make_float2(d[2], d[3]);
        }
    }
}

// ---------------- fused gather1 + gemm2: warp per dst node -----------------
// agg = dinv[d]*(dinv[d]*h[d] + sum dinv[s]*h[s]);  a = relu(agg + b1)
// g_h2[d] = (a @ W2) * dinv[d]
__global__ __launch_bounds__(256) void k_agg_gemm2(const float* __restrict__ W2,
                                                   const float* __restrict__ b1) {
    __shared__ float W2s[HID * NCLS];
    __shared__ float b1s[HID];
    __shared__ float rows[8][HID];
    int tid = threadIdx.x;
    for (int i = tid; i < HID * NCLS; i += 256) W2s[i] = W2[i];
    if (tid < HID) b1s[tid] = b1[tid];
    __syncthreads();

    int w    = tid >> 5;
    int node = blockIdx.x * 8 + w;
    int lane = tid & 31;
    if (node >= N_NODES) return;

    float di = g_dinv[node];

    // self term: dinv[d]*h[d]
    float4 acc = ((const float4*)(g_h + (size_t)node * HID))[lane];
    acc.x *= di; acc.y *= di; acc.z *= di; acc.w *= di;

    int beg = g_rowptr[node], end = g_rowptr[node + 1];
    for (int i = beg; i < end; i += 32) {
        int myidx = i + lane;
        int   s  = (myidx < end) ? g_adj[myidx] : 0;
        float ds = (myidx < end) ? g_dinv[s] : 0.0f;
        int cnt = min(32, end - i);
        int j = 0;
        for (; j + 4 <= cnt; j += 4) {
            int s0 = __shfl_sync(0xFFFFFFFFu, s, j);
            int s1 = __shfl_sync(0xFFFFFFFFu, s, j + 1);
            int s2 = __shfl_sync(0xFFFFFFFFu, s, j + 2);
            int s3 = __shfl_sync(0xFFFFFFFFu, s, j + 3);
            float d0 = __shfl_sync(0xFFFFFFFFu, ds, j);
            float d1 = __shfl_sync(0xFFFFFFFFu, ds, j + 1);
            float d2 = __shfl_sync(0xFFFFFFFFu, ds, j + 2);
            float d3 = __shfl_sync(0xFFFFFFFFu, ds, j + 3);
            float4 v0 = ((const float4*)(g_h + (size_t)s0 * HID))[lane];
            float4 v1 = ((const float4*)(g_h + (size_t)s1 * HID))[lane];
            float4 v2 = ((const float4*)(g_h + (size_t)s2 * HID))[lane];
            float4 v3 = ((const float4*)(g_h + (size_t)s3 * HID))[lane];
            acc.x = fmaf(v0.x, d0, fmaf(v1.x, d1, fmaf(v2.x, d2, fmaf(v3.x, d3, acc.x))));
            acc.y = fmaf(v0.y, d0, fmaf(v1.y, d1, fmaf(v2.y, d2, fmaf(v3.y, d3, acc.y))));
            acc.z = fmaf(v0.z, d0, fmaf(v1.z, d1, fmaf(v2.z, d2, fmaf(v3.z, d3, acc.z))));
            acc.w = fmaf(v0.w, d0, fmaf(v1.w, d1, fmaf(v2.w, d2, fmaf(v3.w, d3, acc.w))));
        }
        for (; j < cnt; j++) {
            int   sj = __shfl_sync(0xFFFFFFFFu, s, j);
            float dj = __shfl_sync(0xFFFFFFFFu, ds, j);
            float4 v = ((const float4*)(g_h + (size_t)sj * HID))[lane];
            acc.x = fmaf(v.x, dj, acc.x);
            acc.y = fmaf(v.y, dj, acc.y);
            acc.z = fmaf(v.z, dj, acc.z);
            acc.w = fmaf(v.w, dj, acc.w);
        }
    }
    // a = relu(acc*di + b1), staged to smem row
    {
        const float4 bb = ((const float4*)b1s)[lane];
        float4 a;
        a.x = fmaxf(fmaf(acc.x, di, bb.x), 0.0f);
        a.y = fmaxf(fmaf(acc.y, di, bb.y), 0.0f);
        a.z = fmaxf(fmaf(acc.z, di, bb.z), 0.0f);
        a.w = fmaxf(fmaf(acc.w, di, bb.w), 0.0f);
        ((float4*)rows[w])[lane] = a;
    }
    __syncwarp();

    float acc2 = 0.0f;
    const float* rw = rows[w];
    #pragma unroll 16
    for (int k = 0; k < HID; k++)
        acc2 = fmaf(rw[k], W2s[k * NCLS + lane], acc2);

    g_h2[(size_t)node * NCLS + lane] = acc2 * di;
}

// ---------------- gather2: warp per dst node, 32 feats ---------------------
__global__ __launch_bounds__(256) void k_gather2(const float* __restrict__ b2,
                                                 float* __restrict__ out) {
    int node = blockIdx.x * 8 + (threadIdx.x >> 5);
    int lane = threadIdx.x & 31;
    if (node >= N_NODES) return;

    float acc = g_h2[(size_t)node * NCLS + lane];

    int beg = g_rowptr[node], end = g_rowptr[node + 1];
    for (int i = beg; i < end; i += 32) {
        int myidx = i + lane;
        int s = (myidx < end) ? g_adj[myidx] : 0;
        int cnt = min(32, end - i);
        int j = 0;
        for (; j + 4 <= cnt; j += 4) {
            int s0 = __shfl_sync(0xFFFFFFFFu, s, j);
            int s1 = __shfl_sync(0xFFFFFFFFu, s, j + 1);
            int s2 = __shfl_sync(0xFFFFFFFFu, s, j + 2);
            int s3 = __shfl_sync(0xFFFFFFFFu, s, j + 3);
            acc += g_h2[(size_t)s0 * NCLS + lane] + g_h2[(size_t)s1 * NCLS + lane]
                 + g_h2[(size_t)s2 * NCLS + lane] + g_h2[(size_t)s3 * NCLS + lane];
        }
        for (; j < cnt; j++) {
            int sj = __shfl_sync(0xFFFFFFFFu, s, j);
            acc += g_h2[(size_t)sj * NCLS + lane];
        }
    }
    out[(size_t)node * NCLS + lane] = acc * g_dinv[node] + b2[lane];
}

// ---------------- launch: CSR build forked onto a second stream ------------
extern "C" void kernel_launch(void* const* d_in, const int* in_sizes, int n_in,
                              void* d_out, int out_size) {
    const float* x  = (const float*)d_in[0];
    const int*   ei = (const int*)  d_in[1];
    const float* W1 = (const float*)d_in[2];
    const float* b1 = (const float*)d_in[3];
    const float* W2 = (const float*)d_in[4];
    const float* b2 = (const float*)d_in[5];
    float* out = (float*)d_out;

    const int E = in_sizes[1] / 2;
    const int* src = ei;
    const int* dst = ei + E;

    static cudaStream_t s2 = nullptr;
    static cudaEvent_t ev_fork = nullptr, ev_join = nullptr;
    static bool attr_set = false;
    if (!s2) {
        cudaStreamCreate(&s2);
        cudaEventCreateWithFlags(&ev_fork, cudaEventDisableTiming);
        cudaEventCreateWithFlags(&ev_join, cudaEventDisableTiming);
    }
    if (!attr_set) {
        cudaFuncSetAttribute(k_gemm1, cudaFuncAttributeMaxDynamicSharedMemorySize, SMEM_BYTES);
        attr_set = true;
    }

    // fork: CSR chain on s2, GEMM chain on the main stream
    cudaEventRecord(ev_fork, 0);
    cudaStreamWaitEvent(s2, ev_fork, 0);

    k_deg_zero  <<<(N_NODES + 255) / 256, 256, 0, s2>>>();
    k_deg_count <<<(E + 255) / 256, 256, 0, s2>>>(dst, E);
    k_scan_block<<<NB_SCAN, 1024, 0, s2>>>();
    k_scan_tops <<<1, 128, 0, s2>>>();
    k_scan_add  <<<NB_SCAN, 1024, 0, s2>>>(E);
    k_fill      <<<(E + 255) / 256, 256, 0, s2>>>(src, dst, E);
    cudaEventRecord(ev_join, s2);

    k_w1t       <<<(HID * (IN_F / 2) + 255) / 256, 256>>>(W1);
    k_gemm1     <<<(N_NODES + 127) / 128, 256, SMEM_BYTES>>>(x);

    // join
    cudaStreamWaitEvent(0, ev_join, 0);

    k_agg_gemm2 <<<(N_NODES + 7) / 8, 256>>>(W2, b1);
    k_gather2   <<<(N_NODES + 7) / 8, 256>>>(b2, out);
}